// round 4
// baseline (speedup 1.0000x reference)
#include <cuda_runtime.h>
#include <cstdint>

#define NMAX 100000
#define EMAX 1600000
#define FULLMASK 0xffffffffu

// ---------------- scratch (static device allocations; no cudaMalloc) -------
__device__ float g_h0[NMAX * 128];
__device__ float g_hA[NMAX * 128];
__device__ float g_hB[NMAX * 128];
__device__ float g_o0[NMAX * 128];
__device__ float g_o1[NMAX * 128];
__device__ int   g_counts[NMAX];
__device__ int   g_rowptr[NMAX + 1];
__device__ int   g_cursor[NMAX];
__device__ int   g_srcs[EMAX];
__device__ int   g_bsums[256];

__device__ __forceinline__ uint32_t f2tf32(float v) {
    uint32_t r;
    asm("cvt.rna.tf32.f32 %0, %1;" : "=r"(r) : "f"(v));
    return r;
}

// mma.sync m16n8k8 tf32 (portable, sm_80+)
__device__ __forceinline__ void mma_tf32(float* d, const uint32_t* a, const uint32_t* b) {
    asm volatile(
        "mma.sync.aligned.m16n8k8.row.col.f32.tf32.tf32.f32 "
        "{%0,%1,%2,%3}, {%4,%5,%6,%7}, {%8,%9}, {%0,%1,%2,%3};"
        : "+f"(d[0]), "+f"(d[1]), "+f"(d[2]), "+f"(d[3])
        : "r"(a[0]), "r"(a[1]), "r"(a[2]), "r"(a[3]), "r"(b[0]), "r"(b[1]));
}

// SMEM layout (floats):  A0 pack | A1 pack | B pack | bias
// A pack: [kstep(16)][mtile(8)][lane(32)][4]   -> 16384 floats (64 KB)
// B pack: [kstep(16)][ntile(16)][lane(32)][2]  -> 16384 floats (64 KB)
static constexpr int OFF_A0   = 0;
static constexpr int OFF_A1   = 16384;
static constexpr int OFF_B    = 32768;
static constexpr int OFF_BIAS = 49152;
static constexpr int SMEM_TC  = (49152 + 128) * 4;   // 197120 bytes

// A-pack index for element (row r in tile, col k)
__device__ __forceinline__ int apack_idx(int r, int k) {
    int kstep = k >> 3, kc = k & 7, mtile = r >> 4, rm = r & 15;
    int lane = (rm & 7) * 4 + (kc & 3);
    int slot = ((rm >> 3) & 1) + ((kc >> 2) << 1);
    return ((kstep * 8 + mtile) * 32 + lane) * 4 + slot;
}
// B-pack index for element W[k][nn]
__device__ __forceinline__ int bpack_idx(int k, int nn) {
    int kstep = k >> 3, kc = k & 7, ntile = nn >> 3, nl = nn & 7;
    int lane = nl * 4 + (kc & 3);
    int slot = kc >> 2;
    return ((kstep * 16 + ntile) * 32 + lane) * 2 + slot;
}

// ---------------- fused SAGE layer on tf32 mma.sync -------------------------
// CTA = one 128-node tile; out = relu(agg @ Wl + h @ Wr + bias).
// do_agg=0 -> embedding: out = relu(in @ Wr + bias).
__global__ __launch_bounds__(512, 1) void k_sage_tc(
    const float4* __restrict__ hin4, const int* __restrict__ srcs,
    const int* __restrict__ rowptr, const float* __restrict__ Wl,
    const float* __restrict__ bias, const float* __restrict__ Wr,
    float* __restrict__ hout, int n, int do_agg)
{
    extern __shared__ float smem[];
    const int tid = threadIdx.x;
    const int wid = tid >> 5;
    const int lane = tid & 31;

    // ---- pack B = Wl (or Wr for embedding-only) ----
    {
        const float* W0 = do_agg ? Wl : Wr;
        for (int idx = tid; idx < 16384; idx += 512) {
            int k = idx >> 7, nn = idx & 127;
            smem[OFF_B + bpack_idx(k, nn)] = __uint_as_float(f2tf32(W0[idx]));
        }
    }
    if (tid < 128) smem[OFF_BIAS + tid] = bias[tid];

    // ---- gather (mean of neighbors) + root row, pack into A0/A1 ----
    {
        const int r   = tid & 127;          // row in tile
        const int cwg = tid >> 7;           // 32-col chunk (0..3)
        const int node = blockIdx.x * 128 + r;
        float acc[32];
        #pragma unroll
        for (int j = 0; j < 32; ++j) acc[j] = 0.f;
        float hroot[32];
        #pragma unroll
        for (int j = 0; j < 32; ++j) hroot[j] = 0.f;

        if (node < n) {
            if (do_agg) {
                int beg = __ldg(&rowptr[node]);
                int end = __ldg(&rowptr[node + 1]);
                const float4* hb = hin4 + (size_t)cwg * 8;
                int e = beg;
                #pragma unroll 1
                for (; e + 2 <= end; e += 2) {
                    int s0 = __ldg(&srcs[e]);
                    int s1 = __ldg(&srcs[e + 1]);
                    const float4* p0 = hb + (size_t)s0 * 32;
                    const float4* p1 = hb + (size_t)s1 * 32;
                    #pragma unroll
                    for (int j = 0; j < 8; ++j) {
                        float4 v0 = __ldg(p0 + j);
                        float4 v1 = __ldg(p1 + j);
                        acc[4 * j + 0] += v0.x + v1.x;
                        acc[4 * j + 1] += v0.y + v1.y;
                        acc[4 * j + 2] += v0.z + v1.z;
                        acc[4 * j + 3] += v0.w + v1.w;
                    }
                }
                if (e < end) {
                    const float4* p0 = hb + (size_t)__ldg(&srcs[e]) * 32;
                    #pragma unroll
                    for (int j = 0; j < 8; ++j) {
                        float4 v0 = __ldg(p0 + j);
                        acc[4 * j + 0] += v0.x; acc[4 * j + 1] += v0.y;
                        acc[4 * j + 2] += v0.z; acc[4 * j + 3] += v0.w;
                    }
                }
                float inv = 1.0f / fmaxf((float)(end - beg), 1.0f);
                #pragma unroll
                for (int j = 0; j < 32; ++j) acc[j] *= inv;
            }
            const float4* pr = hin4 + (size_t)node * 32 + cwg * 8;
            #pragma unroll
            for (int j = 0; j < 8; ++j) {
                float4 v = __ldg(pr + j);
                hroot[4 * j + 0] = v.x; hroot[4 * j + 1] = v.y;
                hroot[4 * j + 2] = v.z; hroot[4 * j + 3] = v.w;
            }
        }
        // staggered pack stores (2-way conflicts instead of 16-way)
        #pragma unroll
        for (int j = 0; j < 32; ++j) {
            int jj = (j + (r & 15)) & 31;
            int k = cwg * 32 + jj;
            if (do_agg)
                smem[OFF_A0 + apack_idx(r, k)] = __uint_as_float(f2tf32(acc[jj]));
            smem[OFF_A1 + apack_idx(r, k)] = __uint_as_float(f2tf32(hroot[jj]));
        }
    }
    __syncthreads();

    // ---- GEMM phase: warp wid -> rows (wid&3)*32.., cols (wid>>2)*32.. ----
    const int wm = wid & 3;          // m block (32 rows)
    const int wn = wid >> 2;         // n block (32 cols)
    float C[2][4][4];
    #pragma unroll
    for (int mt = 0; mt < 2; ++mt)
        #pragma unroll
        for (int nt = 0; nt < 4; ++nt)
            #pragma unroll
            for (int q = 0; q < 4; ++q) C[mt][nt][q] = 0.f;

    const float* A0 = smem + (do_agg ? OFF_A0 : OFF_A1);
    {
        #pragma unroll 4
        for (int ks = 0; ks < 16; ++ks) {
            uint32_t af[2][4], bf[4][2];
            #pragma unroll
            for (int mt = 0; mt < 2; ++mt) {
                const float4 v = *(const float4*)(A0 + ((ks * 8 + wm * 2 + mt) * 32 + lane) * 4);
                af[mt][0] = __float_as_uint(v.x); af[mt][1] = __float_as_uint(v.y);
                af[mt][2] = __float_as_uint(v.z); af[mt][3] = __float_as_uint(v.w);
            }
            #pragma unroll
            for (int nt = 0; nt < 4; ++nt) {
                const float2 v = *(const float2*)(smem + OFF_B + ((ks * 16 + wn * 4 + nt) * 32 + lane) * 2);
                bf[nt][0] = __float_as_uint(v.x); bf[nt][1] = __float_as_uint(v.y);
            }
            #pragma unroll
            for (int mt = 0; mt < 2; ++mt)
                #pragma unroll
                for (int nt = 0; nt < 4; ++nt)
                    mma_tf32(C[mt][nt], af[mt], bf[nt]);
        }
    }

    if (do_agg) {
        __syncthreads();              // everyone done reading B (Wl)
        // repack B = Wr
        for (int idx = tid; idx < 16384; idx += 512) {
            int k = idx >> 7, nn = idx & 127;
            smem[OFF_B + bpack_idx(k, nn)] = __uint_as_float(f2tf32(Wr[idx]));
        }
        __syncthreads();
        const float* A1 = smem + OFF_A1;
        #pragma unroll 4
        for (int ks = 0; ks < 16; ++ks) {
            uint32_t af[2][4], bf[4][2];
            #pragma unroll
            for (int mt = 0; mt < 2; ++mt) {
                const float4 v = *(const float4*)(A1 + ((ks * 8 + wm * 2 + mt) * 32 + lane) * 4);
                af[mt][0] = __float_as_uint(v.x); af[mt][1] = __float_as_uint(v.y);
                af[mt][2] = __float_as_uint(v.z); af[mt][3] = __float_as_uint(v.w);
            }
            #pragma unroll
            for (int nt = 0; nt < 4; ++nt) {
                const float2 v = *(const float2*)(smem + OFF_B + ((ks * 16 + wn * 4 + nt) * 32 + lane) * 2);
                bf[nt][0] = __float_as_uint(v.x); bf[nt][1] = __float_as_uint(v.y);
            }
            #pragma unroll
            for (int mt = 0; mt < 2; ++mt)
                #pragma unroll
                for (int nt = 0; nt < 4; ++nt)
                    mma_tf32(C[mt][nt], af[mt], bf[nt]);
        }
    }

    // ---- epilogue: bias + relu, write [row][col] pairs ----
    {
        const int qrow = lane >> 2;           // t/4
        const int qcol = (lane & 3) * 2;      // (t%4)*2
        #pragma unroll
        for (int mt = 0; mt < 2; ++mt) {
            int r0 = wm * 32 + mt * 16 + qrow;
            int nd0 = blockIdx.x * 128 + r0;
            int nd1 = nd0 + 8;
            #pragma unroll
            for (int nt = 0; nt < 4; ++nt) {
                int col = wn * 32 + nt * 8 + qcol;
                float b0 = smem[OFF_BIAS + col], b1 = smem[OFF_BIAS + col + 1];
                if (nd0 < n) {
                    float2 v;
                    v.x = fmaxf(C[mt][nt][0] + b0, 0.f);
                    v.y = fmaxf(C[mt][nt][1] + b1, 0.f);
                    *(float2*)(hout + (size_t)nd0 * 128 + col) = v;
                }
                if (nd1 < n) {
                    float2 v;
                    v.x = fmaxf(C[mt][nt][2] + b0, 0.f);
                    v.y = fmaxf(C[mt][nt][3] + b1, 0.f);
                    *(float2*)(hout + (size_t)nd1 * 128 + col) = v;
                }
            }
        }
    }
}

// ---------------- CSR build -------------------------------------------------
__global__ void k_count(const int* __restrict__ ed, int* __restrict__ counts, int E)
{
    int i = blockIdx.x * blockDim.x + threadIdx.x;
    if (i < E) atomicAdd(&counts[ed[E + i]], 1);
}

__global__ void k_scan1(const int* __restrict__ counts, int* __restrict__ rowptr,
                        int* __restrict__ bsums, int n)
{
    __shared__ int s[1024];
    int i = blockIdx.x * 1024 + threadIdx.x;
    int v = (i < n) ? counts[i] : 0;
    s[threadIdx.x] = v;
    __syncthreads();
    #pragma unroll
    for (int off = 1; off < 1024; off <<= 1) {
        int t = (threadIdx.x >= off) ? s[threadIdx.x - off] : 0;
        __syncthreads();
        s[threadIdx.x] += t;
        __syncthreads();
    }
    if (i < n) rowptr[i] = s[threadIdx.x] - v;
    if (threadIdx.x == 1023) bsums[blockIdx.x] = s[1023];
}

__global__ void k_scan2(int* __restrict__ bsums, int nb, int* __restrict__ rowptr, int n)
{
    if (threadIdx.x == 0 && blockIdx.x == 0) {
        int run = 0;
        for (int b = 0; b < nb; ++b) { int t = bsums[b]; bsums[b] = run; run += t; }
        rowptr[n] = run;
    }
}

__global__ void k_scan3(int* __restrict__ rowptr, const int* __restrict__ bsums,
                        int* __restrict__ cursor, int n)
{
    int i = blockIdx.x * 1024 + threadIdx.x;
    if (i < n) {
        int v = rowptr[i] + bsums[blockIdx.x];
        rowptr[i] = v;
        cursor[i] = v;
    }
}

__global__ void k_scatter(const int* __restrict__ ed, int* __restrict__ cursor,
                          int* __restrict__ srcs, int E)
{
    int i = blockIdx.x * blockDim.x + threadIdx.x;
    if (i < E) {
        int d = ed[E + i];
        int p = atomicAdd(&cursor[d], 1);
        srcs[p] = ed[i];
    }
}

// ---------------- attention combine ----------------------------------------
__global__ __launch_bounds__(256) void k_att(
    const float4* __restrict__ o0, const float4* __restrict__ o1,
    const float* __restrict__ watt, const float* __restrict__ batt,
    float4* __restrict__ agg, int n)
{
    const int lane = threadIdx.x & 31;
    const int gw = blockIdx.x * (blockDim.x >> 5) + (threadIdx.x >> 5);
    const int nw = gridDim.x * (blockDim.x >> 5);
    const int k0 = lane * 4;
    float wa0[4], wa1[4], wb0[4], wb1[4];
    #pragma unroll
    for (int c = 0; c < 4; ++c) {
        wa0[c] = __ldg(&watt[(k0 + c) * 2 + 0]);
        wa1[c] = __ldg(&watt[(k0 + c) * 2 + 1]);
        wb0[c] = __ldg(&watt[(128 + k0 + c) * 2 + 0]);
        wb1[c] = __ldg(&watt[(128 + k0 + c) * 2 + 1]);
    }
    const float bt0 = __ldg(&batt[0]), bt1 = __ldg(&batt[1]);

    for (int node = gw; node < n; node += nw) {
        float4 a = o0[node * 32 + lane];
        float4 b = o1[node * 32 + lane];
        float p0 = a.x * wa0[0] + a.y * wa0[1] + a.z * wa0[2] + a.w * wa0[3]
                 + b.x * wb0[0] + b.y * wb0[1] + b.z * wb0[2] + b.w * wb0[3];
        float p1 = a.x * wa1[0] + a.y * wa1[1] + a.z * wa1[2] + a.w * wa1[3]
                 + b.x * wb1[0] + b.y * wb1[1] + b.z * wb1[2] + b.w * wb1[3];
        #pragma unroll
        for (int off = 16; off; off >>= 1) {
            p0 += __shfl_xor_sync(FULLMASK, p0, off);
            p1 += __shfl_xor_sync(FULLMASK, p1, off);
        }
        float z0 = p0 + bt0, z1 = p1 + bt1;
        float m = fmaxf(z0, z1);
        float e0 = expf(z0 - m), e1 = expf(z1 - m);
        float inv = 1.0f / (e0 + e1);
        float a0 = e0 * inv, a1 = e1 * inv;
        float4 rr;
        rr.x = a0 * a.x + a1 * b.x;
        rr.y = a0 * a.y + a1 * b.y;
        rr.z = a0 * a.z + a1 * b.z;
        rr.w = a0 * a.w + a1 * b.w;
        agg[node * 32 + lane] = rr;
    }
}

// ---------------- classifier + pattern heads -------------------------------
__global__ __launch_bounds__(256) void k_heads(
    const float4* __restrict__ agg,
    const float* __restrict__ wc1, const float* __restrict__ bc1,
    const float* __restrict__ wc2, const float* __restrict__ bc2,
    const float* __restrict__ wp1, const float* __restrict__ bp1,
    const float* __restrict__ wp2, const float* __restrict__ bp2,
    float* __restrict__ fraud, float* __restrict__ pat, int n)
{
    extern __shared__ float sm[];
    float* sC1 = sm;              // 128*64
    float* sP1 = sC1 + 8192;      // 128*64
    float* sC2 = sP1 + 8192;      // 64*2
    float* sP2 = sC2 + 128;       // 64*5
    float* sBC1 = sP2 + 320;      // 64
    float* sBP1 = sBC1 + 64;      // 64
    float* sBC2 = sBP1 + 64;      // 2
    float* sBP2 = sBC2 + 2;       // 5
    for (int i = threadIdx.x; i < 8192; i += blockDim.x) { sC1[i] = wc1[i]; sP1[i] = wp1[i]; }
    for (int i = threadIdx.x; i < 128;  i += blockDim.x) sC2[i] = wc2[i];
    for (int i = threadIdx.x; i < 320;  i += blockDim.x) sP2[i] = wp2[i];
    for (int i = threadIdx.x; i < 64;   i += blockDim.x) { sBC1[i] = bc1[i]; sBP1[i] = bp1[i]; }
    if (threadIdx.x < 2) sBC2[threadIdx.x] = bc2[threadIdx.x];
    if (threadIdx.x < 5) sBP2[threadIdx.x] = bp2[threadIdx.x];
    __syncthreads();

    const int lane = threadIdx.x & 31;
    const int gw = blockIdx.x * (blockDim.x >> 5) + (threadIdx.x >> 5);
    const int nw = gridDim.x * (blockDim.x >> 5);
    const float2* sC1v = (const float2*)sC1;
    const float2* sP1v = (const float2*)sP1;

    const int hA = 2 * lane, hBb = 2 * lane + 1;
    const float c2a0 = sC2[hA * 2 + 0], c2a1 = sC2[hA * 2 + 1];
    const float c2b0 = sC2[hBb * 2 + 0], c2b1 = sC2[hBb * 2 + 1];
    float p2a[5], p2b[5];
    #pragma unroll
    for (int j = 0; j < 5; ++j) { p2a[j] = sP2[hA * 5 + j]; p2b[j] = sP2[hBb * 5 + j]; }
    const float bC1a = sBC1[hA], bC1b = sBC1[hBb];
    const float bP1a = sBP1[hA], bP1b = sBP1[hBb];
    const float bC2_0 = sBC2[0], bC2_1 = sBC2[1];
    float bP2v[5];
    #pragma unroll
    for (int j = 0; j < 5; ++j) bP2v[j] = sBP2[j];

    for (int node = gw; node < n; node += nw) {
        float4 ar = agg[node * 32 + lane];
        float hc0 = bC1a, hc1 = bC1b, hp0 = bP1a, hp1 = bP1b;
        #pragma unroll 4
        for (int kk = 0; kk < 32; ++kk) {
            float av[4];
            av[0] = __shfl_sync(FULLMASK, ar.x, kk);
            av[1] = __shfl_sync(FULLMASK, ar.y, kk);
            av[2] = __shfl_sync(FULLMASK, ar.z, kk);
            av[3] = __shfl_sync(FULLMASK, ar.w, kk);
            #pragma unroll
            for (int j = 0; j < 4; ++j) {
                int k = kk * 4 + j;
                float2 wc = sC1v[k * 32 + lane];
                float2 wp = sP1v[k * 32 + lane];
                hc0 += av[j] * wc.x; hc1 += av[j] * wc.y;
                hp0 += av[j] * wp.x; hp1 += av[j] * wp.y;
            }
        }
        hc0 = fmaxf(hc0, 0.f); hc1 = fmaxf(hc1, 0.f);
        hp0 = fmaxf(hp0, 0.f); hp1 = fmaxf(hp1, 0.f);

        float f0 = hc0 * c2a0 + hc1 * c2b0;
        float f1 = hc0 * c2a1 + hc1 * c2b1;
        float q[5];
        #pragma unroll
        for (int j = 0; j < 5; ++j) q[j] = hp0 * p2a[j] + hp1 * p2b[j];
        #pragma unroll
        for (int off = 16; off; off >>= 1) {
            f0 += __shfl_xor_sync(FULLMASK, f0, off);
            f1 += __shfl_xor_sync(FULLMASK, f1, off);
            #pragma unroll
            for (int j = 0; j < 5; ++j) q[j] += __shfl_xor_sync(FULLMASK, q[j], off);
        }
        if (lane == 0) {
            fraud[node * 2 + 0] = f0 + bC2_0;
            fraud[node * 2 + 1] = f1 + bC2_1;
            #pragma unroll
            for (int j = 0; j < 5; ++j) pat[node * 5 + j] = q[j] + bP2v[j];
        }
    }
}

// ---------------- launcher --------------------------------------------------
extern "C" void kernel_launch(void* const* d_in, const int* in_sizes, int n_in,
                              void* d_out, int out_size)
{
    const float* x     = (const float*)d_in[0];
    const int*   e0    = (const int*)  d_in[1];
    const int*   e1    = (const int*)  d_in[2];
    const float* w_emb = (const float*)d_in[3];
    const float* b_emb = (const float*)d_in[4];
    const float* Wl    = (const float*)d_in[5];
    const float* bl    = (const float*)d_in[6];
    const float* Wr    = (const float*)d_in[7];
    const float* w_att = (const float*)d_in[8];
    const float* b_att = (const float*)d_in[9];
    const float* w_c1  = (const float*)d_in[10];
    const float* b_c1  = (const float*)d_in[11];
    const float* w_c2  = (const float*)d_in[12];
    const float* b_c2  = (const float*)d_in[13];
    const float* w_p1  = (const float*)d_in[14];
    const float* b_p1  = (const float*)d_in[15];
    const float* w_p2  = (const float*)d_in[16];
    const float* b_p2  = (const float*)d_in[17];

    int n = in_sizes[0] / 128; if (n > NMAX) n = NMAX;
    int E = in_sizes[1] / 2;   if (E > EMAX) E = EMAX;

    float* out_fraud = (float*)d_out;
    float* out_pat   = out_fraud + (size_t)n * 2;
    float* out_agg   = out_pat   + (size_t)n * 5;

    float *h0, *hA, *hB, *o0, *o1;
    int *counts, *rowptr, *cursor, *srcs, *bsums;
    cudaGetSymbolAddress((void**)&h0, g_h0);
    cudaGetSymbolAddress((void**)&hA, g_hA);
    cudaGetSymbolAddress((void**)&hB, g_hB);
    cudaGetSymbolAddress((void**)&o0, g_o0);
    cudaGetSymbolAddress((void**)&o1, g_o1);
    cudaGetSymbolAddress((void**)&counts, g_counts);
    cudaGetSymbolAddress((void**)&rowptr, g_rowptr);
    cudaGetSymbolAddress((void**)&cursor, g_cursor);
    cudaGetSymbolAddress((void**)&srcs, g_srcs);
    cudaGetSymbolAddress((void**)&bsums, g_bsums);

    const int SM_HEADS = (8192 + 8192 + 128 + 320 + 64 + 64 + 2 + 5) * 4;
    cudaFuncSetAttribute(k_sage_tc, cudaFuncAttributeMaxDynamicSharedMemorySize, SMEM_TC);
    cudaFuncSetAttribute(k_heads,   cudaFuncAttributeMaxDynamicSharedMemorySize, SM_HEADS);

    const int tiles = (n + 127) / 128;

    // node embedding: relu(x @ w_emb + b_emb)
    k_sage_tc<<<tiles, 512, SMEM_TC>>>((const float4*)x, nullptr, nullptr,
                                       nullptr, b_emb, w_emb, h0, n, 0);

    const int NB = (n + 1023) / 1024;
    for (int et = 0; et < 2; ++et) {
        const int* ed = et ? e1 : e0;
        cudaMemsetAsync(counts, 0, n * sizeof(int));
        k_count<<<(E + 255) / 256, 256>>>(ed, counts, E);
        k_scan1<<<NB, 1024>>>(counts, rowptr, bsums, n);
        k_scan2<<<1, 32>>>(bsums, NB, rowptr, n);
        k_scan3<<<NB, 1024>>>(rowptr, bsums, cursor, n);
        k_scatter<<<(E + 255) / 256, 256>>>(ed, cursor, srcs, E);

        const float* hin = h0;
        float* outs[3] = { hA, hB, et ? o1 : o0 };
        for (int l = 0; l < 3; ++l) {
            const float* Wlp = Wl + (size_t)(et * 3 + l) * 128 * 128;
            const float* blp = bl + (size_t)(et * 3 + l) * 128;
            const float* Wrp = Wr + (size_t)(et * 3 + l) * 128 * 128;
            k_sage_tc<<<tiles, 512, SMEM_TC>>>((const float4*)hin, srcs, rowptr,
                                               Wlp, blp, Wrp, outs[l], n, 1);
            hin = outs[l];
        }
    }

    k_att<<<1024, 256>>>((const float4*)o0, (const float4*)o1, w_att, b_att,
                         (float4*)out_agg, n);
    k_heads<<<592, 256, SM_HEADS>>>((const float4*)out_agg,
                                    w_c1, b_c1, w_c2, b_c2,
                                    w_p1, b_p1, w_p2, b_p2,
                                    out_fraud, out_pat, n);
}

// round 5
// speedup vs baseline: 1.6727x; 1.6727x over previous
#include <cuda_runtime.h>
#include <cuda_fp16.h>
#include <cstdint>

#define NMAX 100000
#define EMAX 1600000
#define FULLMASK 0xffffffffu

// ---------------- scratch (static device allocations; no cudaMalloc) -------
__device__ __half g_h0[NMAX * 128];
__device__ __half g_hA[NMAX * 128];
__device__ __half g_hB[NMAX * 128];
__device__ __half g_o0[NMAX * 128];
__device__ __half g_o1[NMAX * 128];
__device__ int    g_counts[NMAX];
__device__ int    g_rowptr[NMAX + 1];
__device__ int    g_cursor[NMAX];
__device__ int    g_srcs[EMAX];
__device__ int    g_bsums[256];

__device__ __forceinline__ uint32_t f2tf32(float v) {
    uint32_t r;
    asm("cvt.rna.tf32.f32 %0, %1;" : "=r"(r) : "f"(v));
    return r;
}

// mma.sync m16n8k8 tf32 (portable, sm_80+)
__device__ __forceinline__ void mma_tf32(float* d, const uint32_t* a, const uint32_t* b) {
    asm volatile(
        "mma.sync.aligned.m16n8k8.row.col.f32.tf32.tf32.f32 "
        "{%0,%1,%2,%3}, {%4,%5,%6,%7}, {%8,%9}, {%0,%1,%2,%3};"
        : "+f"(d[0]), "+f"(d[1]), "+f"(d[2]), "+f"(d[3])
        : "r"(a[0]), "r"(a[1]), "r"(a[2]), "r"(a[3]), "r"(b[0]), "r"(b[1]));
}

// SMEM (floats): A0[128][132] | A1[128][132] | B[128][132] | bias[128]
static constexpr int LDA    = 132;
static constexpr int F_A0   = 0;
static constexpr int F_A1   = 128 * LDA;          // 16896
static constexpr int F_B    = 2 * 128 * LDA;      // 33792
static constexpr int F_BIAS = 3 * 128 * LDA;      // 50688
static constexpr int SMEM_TC = (3 * 128 * LDA + 128) * 4;   // 203264 B

__device__ __forceinline__ void acc_h4(float& a0, float& a1, float& a2, float& a3, uint2 u) {
    float2 f0 = __half22float2(*reinterpret_cast<const __half2*>(&u.x));
    float2 f1 = __half22float2(*reinterpret_cast<const __half2*>(&u.y));
    a0 += f0.x; a1 += f0.y; a2 += f1.x; a3 += f1.y;
}

__device__ __forceinline__ void gemm_accum(const float* __restrict__ As,
                                           const float* __restrict__ Bs,
                                           int wm, int wn, int tr, int tc,
                                           float C[2][4][4]) {
    #pragma unroll 4
    for (int ks = 0; ks < 16; ++ks) {
        uint32_t af[2][4], bf[4][2];
        #pragma unroll
        for (int mt = 0; mt < 2; ++mt) {
            const float* p = As + (wm * 32 + mt * 16 + tr) * LDA + ks * 8 + tc;
            af[mt][0] = __float_as_uint(p[0]);
            af[mt][1] = __float_as_uint(p[8 * LDA]);
            af[mt][2] = __float_as_uint(p[4]);
            af[mt][3] = __float_as_uint(p[8 * LDA + 4]);
        }
        #pragma unroll
        for (int nt = 0; nt < 4; ++nt) {
            const float* p = Bs + (wn * 32 + nt * 8 + tr) * LDA + ks * 8 + tc;
            bf[nt][0] = __float_as_uint(p[0]);
            bf[nt][1] = __float_as_uint(p[4]);
        }
        #pragma unroll
        for (int mt = 0; mt < 2; ++mt)
            #pragma unroll
            for (int nt = 0; nt < 4; ++nt)
                mma_tf32(C[mt][nt], af[mt], bf[nt]);
    }
}

// ---------------- fused SAGE layer on tf32 mma.sync -------------------------
// CTA = one 128-node tile; out = relu(agg @ Wl + h @ Wr + bias), h in fp16.
// do_agg=0 -> embedding: input is fp32 x, out = relu(x @ Wr + bias).
__global__ __launch_bounds__(512, 1) void k_sage_tc(
    const void* __restrict__ hin_v, const int* __restrict__ srcs,
    const int* __restrict__ rowptr, const float* __restrict__ Wl,
    const float* __restrict__ bias, const float* __restrict__ Wr,
    __half* __restrict__ hout, int n, int do_agg)
{
    extern __shared__ float smem[];
    const int tid = threadIdx.x;
    const int wid = tid >> 5;
    const int lane = tid & 31;

    // ---- pack B = Wl (or Wr for embedding): Bt[nn][k], tf32-rounded ----
    {
        const float* W0 = do_agg ? Wl : Wr;
        for (int idx = tid; idx < 16384; idx += 512) {
            int k = idx >> 7, nn = idx & 127;
            smem[F_B + nn * LDA + k] = __uint_as_float(f2tf32(W0[idx]));
        }
    }
    if (tid < 128) smem[F_BIAS + tid] = bias[tid];

    // ---- warp-cooperative gather: warp owns 8 rows, 32 lanes span 128 cols
    #pragma unroll 1
    for (int i = 0; i < 8; ++i) {
        const int row  = wid * 8 + i;
        const int node = blockIdx.x * 128 + row;
        float a0 = 0.f, a1 = 0.f, a2 = 0.f, a3 = 0.f;     // mean-agg (4 cols)
        float r0 = 0.f, r1 = 0.f, r2 = 0.f, r3 = 0.f;     // root row
        if (node < n) {
            if (do_agg) {
                const __half* hin = (const __half*)hin_v;
                const int beg = __ldg(&rowptr[node]);
                const int end = __ldg(&rowptr[node + 1]);
                int e = beg;
                #pragma unroll 1
                for (; e + 4 <= end; e += 4) {
                    int s0 = __ldg(&srcs[e + 0]);
                    int s1 = __ldg(&srcs[e + 1]);
                    int s2 = __ldg(&srcs[e + 2]);
                    int s3 = __ldg(&srcs[e + 3]);
                    uint2 u0 = __ldg((const uint2*)(hin + (size_t)s0 * 128) + lane);
                    uint2 u1 = __ldg((const uint2*)(hin + (size_t)s1 * 128) + lane);
                    uint2 u2 = __ldg((const uint2*)(hin + (size_t)s2 * 128) + lane);
                    uint2 u3 = __ldg((const uint2*)(hin + (size_t)s3 * 128) + lane);
                    acc_h4(a0, a1, a2, a3, u0);
                    acc_h4(a0, a1, a2, a3, u1);
                    acc_h4(a0, a1, a2, a3, u2);
                    acc_h4(a0, a1, a2, a3, u3);
                }
                for (; e < end; ++e) {
                    uint2 u = __ldg((const uint2*)(hin + (size_t)__ldg(&srcs[e]) * 128) + lane);
                    acc_h4(a0, a1, a2, a3, u);
                }
                float inv = 1.0f / fmaxf((float)(end - beg), 1.0f);
                a0 *= inv; a1 *= inv; a2 *= inv; a3 *= inv;
                uint2 u = __ldg((const uint2*)(hin + (size_t)node * 128) + lane);
                float2 f0 = __half22float2(*reinterpret_cast<const __half2*>(&u.x));
                float2 f1 = __half22float2(*reinterpret_cast<const __half2*>(&u.y));
                r0 = f0.x; r1 = f0.y; r2 = f1.x; r3 = f1.y;
            } else {
                const float4 v = __ldg((const float4*)hin_v + (size_t)node * 32 + lane);
                r0 = v.x; r1 = v.y; r2 = v.z; r3 = v.w;
            }
        }
        float4 t1;
        t1.x = __uint_as_float(f2tf32(r0)); t1.y = __uint_as_float(f2tf32(r1));
        t1.z = __uint_as_float(f2tf32(r2)); t1.w = __uint_as_float(f2tf32(r3));
        *(float4*)(smem + F_A1 + row * LDA + 4 * lane) = t1;
        if (do_agg) {
            float4 t0;
            t0.x = __uint_as_float(f2tf32(a0)); t0.y = __uint_as_float(f2tf32(a1));
            t0.z = __uint_as_float(f2tf32(a2)); t0.w = __uint_as_float(f2tf32(a3));
            *(float4*)(smem + F_A0 + row * LDA + 4 * lane) = t0;
        }
    }
    __syncthreads();

    // ---- GEMM: warp wid -> rows (wid&3)*32.., cols (wid>>2)*32.. ----
    const int wm = wid & 3;
    const int wn = wid >> 2;
    const int tr = lane >> 2;
    const int tc = lane & 3;
    float C[2][4][4];
    #pragma unroll
    for (int mt = 0; mt < 2; ++mt)
        #pragma unroll
        for (int nt = 0; nt < 4; ++nt)
            #pragma unroll
            for (int q = 0; q < 4; ++q) C[mt][nt][q] = 0.f;

    if (do_agg) {
        gemm_accum(smem + F_A0, smem + F_B, wm, wn, tr, tc, C);   // agg @ Wl
        __syncthreads();
        for (int idx = tid; idx < 16384; idx += 512) {            // repack B=Wr
            int k = idx >> 7, nn = idx & 127;
            smem[F_B + nn * LDA + k] = __uint_as_float(f2tf32(Wr[idx]));
        }
        __syncthreads();
    }
    gemm_accum(smem + F_A1, smem + F_B, wm, wn, tr, tc, C);       // h @ Wr

    // ---- epilogue: bias + relu -> fp16 ----
    {
        #pragma unroll
        for (int mt = 0; mt < 2; ++mt) {
            int r0i = wm * 32 + mt * 16 + tr;
            int nd0 = blockIdx.x * 128 + r0i;
            int nd1 = nd0 + 8;
            #pragma unroll
            for (int nt = 0; nt < 4; ++nt) {
                int col = wn * 32 + nt * 8 + tc * 2;
                float b0 = smem[F_BIAS + col], b1 = smem[F_BIAS + col + 1];
                if (nd0 < n) {
                    __half2 v = __floats2half2_rn(fmaxf(C[mt][nt][0] + b0, 0.f),
                                                  fmaxf(C[mt][nt][1] + b1, 0.f));
                    *(__half2*)(hout + (size_t)nd0 * 128 + col) = v;
                }
                if (nd1 < n) {
                    __half2 v = __floats2half2_rn(fmaxf(C[mt][nt][2] + b0, 0.f),
                                                  fmaxf(C[mt][nt][3] + b1, 0.f));
                    *(__half2*)(hout + (size_t)nd1 * 128 + col) = v;
                }
            }
        }
    }
}

// ---------------- CSR build -------------------------------------------------
__global__ void k_count(const int* __restrict__ ed, int* __restrict__ counts, int E)
{
    int i = blockIdx.x * blockDim.x + threadIdx.x;
    if (i < E) atomicAdd(&counts[ed[E + i]], 1);
}

__global__ void k_scan1(const int* __restrict__ counts, int* __restrict__ rowptr,
                        int* __restrict__ bsums, int n)
{
    __shared__ int s[1024];
    int i = blockIdx.x * 1024 + threadIdx.x;
    int v = (i < n) ? counts[i] : 0;
    s[threadIdx.x] = v;
    __syncthreads();
    #pragma unroll
    for (int off = 1; off < 1024; off <<= 1) {
        int t = (threadIdx.x >= off) ? s[threadIdx.x - off] : 0;
        __syncthreads();
        s[threadIdx.x] += t;
        __syncthreads();
    }
    if (i < n) rowptr[i] = s[threadIdx.x] - v;
    if (threadIdx.x == 1023) bsums[blockIdx.x] = s[1023];
}

__global__ void k_scan2(int* __restrict__ bsums, int nb, int* __restrict__ rowptr, int n)
{
    if (threadIdx.x == 0 && blockIdx.x == 0) {
        int run = 0;
        for (int b = 0; b < nb; ++b) { int t = bsums[b]; bsums[b] = run; run += t; }
        rowptr[n] = run;
    }
}

__global__ void k_scan3(int* __restrict__ rowptr, const int* __restrict__ bsums,
                        int* __restrict__ cursor, int n)
{
    int i = blockIdx.x * 1024 + threadIdx.x;
    if (i < n) {
        int v = rowptr[i] + bsums[blockIdx.x];
        rowptr[i] = v;
        cursor[i] = v;
    }
}

__global__ void k_scatter(const int* __restrict__ ed, int* __restrict__ cursor,
                          int* __restrict__ srcs, int E)
{
    int i = blockIdx.x * blockDim.x + threadIdx.x;
    if (i < E) {
        int d = ed[E + i];
        int p = atomicAdd(&cursor[d], 1);
        srcs[p] = ed[i];
    }
}

// ---------------- attention combine (fp16 in, fp32 out) ---------------------
__global__ __launch_bounds__(256) void k_att(
    const __half* __restrict__ o0, const __half* __restrict__ o1,
    const float* __restrict__ watt, const float* __restrict__ batt,
    float4* __restrict__ agg, int n)
{
    const int lane = threadIdx.x & 31;
    const int gw = blockIdx.x * (blockDim.x >> 5) + (threadIdx.x >> 5);
    const int nw = gridDim.x * (blockDim.x >> 5);
    const int k0 = lane * 4;
    float wa0[4], wa1[4], wb0[4], wb1[4];
    #pragma unroll
    for (int c = 0; c < 4; ++c) {
        wa0[c] = __ldg(&watt[(k0 + c) * 2 + 0]);
        wa1[c] = __ldg(&watt[(k0 + c) * 2 + 1]);
        wb0[c] = __ldg(&watt[(128 + k0 + c) * 2 + 0]);
        wb1[c] = __ldg(&watt[(128 + k0 + c) * 2 + 1]);
    }
    const float bt0 = __ldg(&batt[0]), bt1 = __ldg(&batt[1]);

    for (int node = gw; node < n; node += nw) {
        uint2 ua = __ldg((const uint2*)(o0 + (size_t)node * 128) + lane);
        uint2 ub = __ldg((const uint2*)(o1 + (size_t)node * 128) + lane);
        float2 a01 = __half22float2(*reinterpret_cast<const __half2*>(&ua.x));
        float2 a23 = __half22float2(*reinterpret_cast<const __half2*>(&ua.y));
        float2 b01 = __half22float2(*reinterpret_cast<const __half2*>(&ub.x));
        float2 b23 = __half22float2(*reinterpret_cast<const __half2*>(&ub.y));
        float p0 = a01.x * wa0[0] + a01.y * wa0[1] + a23.x * wa0[2] + a23.y * wa0[3]
                 + b01.x * wb0[0] + b01.y * wb0[1] + b23.x * wb0[2] + b23.y * wb0[3];
        float p1 = a01.x * wa1[0] + a01.y * wa1[1] + a23.x * wa1[2] + a23.y * wa1[3]
                 + b01.x * wb1[0] + b01.y * wb1[1] + b23.x * wb1[2] + b23.y * wb1[3];
        #pragma unroll
        for (int off = 16; off; off >>= 1) {
            p0 += __shfl_xor_sync(FULLMASK, p0, off);
            p1 += __shfl_xor_sync(FULLMASK, p1, off);
        }
        float z0 = p0 + bt0, z1 = p1 + bt1;
        float m = fmaxf(z0, z1);
        float e0 = expf(z0 - m), e1 = expf(z1 - m);
        float inv = 1.0f / (e0 + e1);
        float w0 = e0 * inv, w1 = e1 * inv;
        float4 rr;
        rr.x = w0 * a01.x + w1 * b01.x;
        rr.y = w0 * a01.y + w1 * b01.y;
        rr.z = w0 * a23.x + w1 * b23.x;
        rr.w = w0 * a23.y + w1 * b23.y;
        agg[node * 32 + lane] = rr;
    }
}

// ---------------- classifier + pattern heads -------------------------------
__global__ __launch_bounds__(256) void k_heads(
    const float4* __restrict__ agg,
    const float* __restrict__ wc1, const float* __restrict__ bc1,
    const float* __restrict__ wc2, const float* __restrict__ bc2,
    const float* __restrict__ wp1, const float* __restrict__ bp1,
    const float* __restrict__ wp2, const float* __restrict__ bp2,
    float* __restrict__ fraud, float* __restrict__ pat, int n)
{
    extern __shared__ float sm[];
    float* sC1 = sm;              // 128*64
    float* sP1 = sC1 + 8192;      // 128*64
    float* sC2 = sP1 + 8192;      // 64*2
    float* sP2 = sC2 + 128;       // 64*5
    float* sBC1 = sP2 + 320;      // 64
    float* sBP1 = sBC1 + 64;      // 64
    float* sBC2 = sBP1 + 64;      // 2
    float* sBP2 = sBC2 + 2;       // 5
    for (int i = threadIdx.x; i < 8192; i += blockDim.x) { sC1[i] = wc1[i]; sP1[i] = wp1[i]; }
    for (int i = threadIdx.x; i < 128;  i += blockDim.x) sC2[i] = wc2[i];
    for (int i = threadIdx.x; i < 320;  i += blockDim.x) sP2[i] = wp2[i];
    for (int i = threadIdx.x; i < 64;   i += blockDim.x) { sBC1[i] = bc1[i]; sBP1[i] = bp1[i]; }
    if (threadIdx.x < 2) sBC2[threadIdx.x] = bc2[threadIdx.x];
    if (threadIdx.x < 5) sBP2[threadIdx.x] = bp2[threadIdx.x];
    __syncthreads();

    const int lane = threadIdx.x & 31;
    const int gw = blockIdx.x * (blockDim.x >> 5) + (threadIdx.x >> 5);
    const int nw = gridDim.x * (blockDim.x >> 5);
    const float2* sC1v = (const float2*)sC1;
    const float2* sP1v = (const float2*)sP1;

    const int hA = 2 * lane, hBb = 2 * lane + 1;
    const float c2a0 = sC2[hA * 2 + 0], c2a1 = sC2[hA * 2 + 1];
    const float c2b0 = sC2[hBb * 2 + 0], c2b1 = sC2[hBb * 2 + 1];
    float p2a[5], p2b[5];
    #pragma unroll
    for (int j = 0; j < 5; ++j) { p2a[j] = sP2[hA * 5 + j]; p2b[j] = sP2[hBb * 5 + j]; }
    const float bC1a = sBC1[hA], bC1b = sBC1[hBb];
    const float bP1a = sBP1[hA], bP1b = sBP1[hBb];
    const float bC2_0 = sBC2[0], bC2_1 = sBC2[1];
    float bP2v[5];
    #pragma unroll
    for (int j = 0; j < 5; ++j) bP2v[j] = sBP2[j];

    for (int node = gw; node < n; node += nw) {
        float4 ar = agg[node * 32 + lane];
        float hc0 = bC1a, hc1 = bC1b, hp0 = bP1a, hp1 = bP1b;
        #pragma unroll 4
        for (int kk = 0; kk < 32; ++kk) {
            float av[4];
            av[0] = __shfl_sync(FULLMASK, ar.x, kk);
            av[1] = __shfl_sync(FULLMASK, ar.y, kk);
            av[2] = __shfl_sync(FULLMASK, ar.z, kk);
            av[3] = __shfl_sync(FULLMASK, ar.w, kk);
            #pragma unroll
            for (int j = 0; j < 4; ++j) {
                int k = kk * 4 + j;
                float2 wc = sC1v[k * 32 + lane];
                float2 wp = sP1v[k * 32 + lane];
                hc0 += av[j] * wc.x; hc1 += av[j] * wc.y;
                hp0 += av[j] * wp.x; hp1 += av[j] * wp.y;
            }
        }
        hc0 = fmaxf(hc0, 0.f); hc1 = fmaxf(hc1, 0.f);
        hp0 = fmaxf(hp0, 0.f); hp1 = fmaxf(hp1, 0.f);

        float f0 = hc0 * c2a0 + hc1 * c2b0;
        float f1 = hc0 * c2a1 + hc1 * c2b1;
        float q[5];
        #pragma unroll
        for (int j = 0; j < 5; ++j) q[j] = hp0 * p2a[j] + hp1 * p2b[j];
        #pragma unroll
        for (int off = 16; off; off >>= 1) {
            f0 += __shfl_xor_sync(FULLMASK, f0, off);
            f1 += __shfl_xor_sync(FULLMASK, f1, off);
            #pragma unroll
            for (int j = 0; j < 5; ++j) q[j] += __shfl_xor_sync(FULLMASK, q[j], off);
        }
        if (lane == 0) {
            fraud[node * 2 + 0] = f0 + bC2_0;
            fraud[node * 2 + 1] = f1 + bC2_1;
            #pragma unroll
            for (int j = 0; j < 5; ++j) pat[node * 5 + j] = q[j] + bP2v[j];
        }
    }
}

// ---------------- launcher --------------------------------------------------
extern "C" void kernel_launch(void* const* d_in, const int* in_sizes, int n_in,
                              void* d_out, int out_size)
{
    const float* x     = (const float*)d_in[0];
    const int*   e0    = (const int*)  d_in[1];
    const int*   e1    = (const int*)  d_in[2];
    const float* w_emb = (const float*)d_in[3];
    const float* b_emb = (const float*)d_in[4];
    const float* Wl    = (const float*)d_in[5];
    const float* bl    = (const float*)d_in[6];
    const float* Wr    = (const float*)d_in[7];
    const float* w_att = (const float*)d_in[8];
    const float* b_att = (const float*)d_in[9];
    const float* w_c1  = (const float*)d_in[10];
    const float* b_c1  = (const float*)d_in[11];
    const float* w_c2  = (const float*)d_in[12];
    const float* b_c2  = (const float*)d_in[13];
    const float* w_p1  = (const float*)d_in[14];
    const float* b_p1  = (const float*)d_in[15];
    const float* w_p2  = (const float*)d_in[16];
    const float* b_p2  = (const float*)d_in[17];

    int n = in_sizes[0] / 128; if (n > NMAX) n = NMAX;
    int E = in_sizes[1] / 2;   if (E > EMAX) E = EMAX;

    float* out_fraud = (float*)d_out;
    float* out_pat   = out_fraud + (size_t)n * 2;
    float* out_agg   = out_pat   + (size_t)n * 5;

    __half *h0, *hA, *hB, *o0, *o1;
    int *counts, *rowptr, *cursor, *srcs, *bsums;
    cudaGetSymbolAddress((void**)&h0, g_h0);
    cudaGetSymbolAddress((void**)&hA, g_hA);
    cudaGetSymbolAddress((void**)&hB, g_hB);
    cudaGetSymbolAddress((void**)&o0, g_o0);
    cudaGetSymbolAddress((void**)&o1, g_o1);
    cudaGetSymbolAddress((void**)&counts, g_counts);
    cudaGetSymbolAddress((void**)&rowptr, g_rowptr);
    cudaGetSymbolAddress((void**)&cursor, g_cursor);
    cudaGetSymbolAddress((void**)&srcs, g_srcs);
    cudaGetSymbolAddress((void**)&bsums, g_bsums);

    const int SM_HEADS = (8192 + 8192 + 128 + 320 + 64 + 64 + 2 + 5) * 4;
    cudaFuncSetAttribute(k_sage_tc, cudaFuncAttributeMaxDynamicSharedMemorySize, SMEM_TC);
    cudaFuncSetAttribute(k_heads,   cudaFuncAttributeMaxDynamicSharedMemorySize, SM_HEADS);

    const int tiles = (n + 127) / 128;

    // node embedding: relu(x @ w_emb + b_emb)
    k_sage_tc<<<tiles, 512, SMEM_TC>>>(x, nullptr, nullptr,
                                       nullptr, b_emb, w_emb, h0, n, 0);

    const int NB = (n + 1023) / 1024;
    for (int et = 0; et < 2; ++et) {
        const int* ed = et ? e1 : e0;
        cudaMemsetAsync(counts, 0, n * sizeof(int));
        k_count<<<(E + 255) / 256, 256>>>(ed, counts, E);
        k_scan1<<<NB, 1024>>>(counts, rowptr, bsums, n);
        k_scan2<<<1, 32>>>(bsums, NB, rowptr, n);
        k_scan3<<<NB, 1024>>>(rowptr, bsums, cursor, n);
        k_scatter<<<(E + 255) / 256, 256>>>(ed, cursor, srcs, E);

        const __half* hin = h0;
        __half* outs[3] = { hA, hB, et ? o1 : o0 };
        for (int l = 0; l < 3; ++l) {
            const float* Wlp = Wl + (size_t)(et * 3 + l) * 128 * 128;
            const float* blp = bl + (size_t)(et * 3 + l) * 128;
            const float* Wrp = Wr + (size_t)(et * 3 + l) * 128 * 128;
            k_sage_tc<<<tiles, 512, SMEM_TC>>>(hin, srcs, rowptr,
                                               Wlp, blp, Wrp, outs[l], n, 1);
            hin = outs[l];
        }
    }

    k_att<<<1024, 256>>>(o0, o1, w_att, b_att, (float4*)out_agg, n);
    k_heads<<<592, 256, SM_HEADS>>>((const float4*)out_agg,
                                    w_c1, b_c1, w_c2, b_c2,
                                    w_p1, b_p1, w_p2, b_p2,
                                    out_fraud, out_pat, n);
}

// round 7
// speedup vs baseline: 1.7721x; 1.0594x over previous
#include <cuda_runtime.h>
#include <cuda_fp16.h>
#include <cstdint>

#define NMAX 100000
#define EMAX 1600000
#define FULLMASK 0xffffffffu

// ---------------- scratch (static device allocations; no cudaMalloc) -------
__device__ __half g_h0[NMAX * 128];
__device__ __half g_hA[NMAX * 128];
__device__ __half g_hB[NMAX * 128];
__device__ __half g_o0[NMAX * 128];
__device__ __half g_o1[NMAX * 128];
__device__ __half g_agg[NMAX * 128];
__device__ int    g_counts[NMAX];
__device__ int    g_rowptr[NMAX + 1];
__device__ int    g_cursor[NMAX];
__device__ int    g_srcs[EMAX];
__device__ int    g_scan_val[256];
__device__ int    g_scan_flag[256];

__device__ __forceinline__ uint32_t f2tf32(float v) {
    uint32_t r;
    asm("cvt.rna.tf32.f32 %0, %1;" : "=r"(r) : "f"(v));
    return r;
}

// mma.sync m16n8k8 tf32 (portable, sm_80+)
__device__ __forceinline__ void mma_tf32(float* d, const uint32_t* a, const uint32_t* b) {
    asm volatile(
        "mma.sync.aligned.m16n8k8.row.col.f32.tf32.tf32.f32 "
        "{%0,%1,%2,%3}, {%4,%5,%6,%7}, {%8,%9}, {%0,%1,%2,%3};"
        : "+f"(d[0]), "+f"(d[1]), "+f"(d[2]), "+f"(d[3])
        : "r"(a[0]), "r"(a[1]), "r"(a[2]), "r"(a[3]), "r"(b[0]), "r"(b[1]));
}

// SMEM (floats): A0[128][132] | A1[128][132] | B[128][132] | bias[128]
static constexpr int LDA    = 132;
static constexpr int F_A0   = 0;
static constexpr int F_A1   = 128 * LDA;
static constexpr int F_B    = 2 * 128 * LDA;
static constexpr int F_BIAS = 3 * 128 * LDA;
static constexpr int SMEM_TC = (3 * 128 * LDA + 128) * 4;   // 203264 B

__device__ __forceinline__ void gemm_accum(const float* __restrict__ As,
                                           const float* __restrict__ Bs,
                                           int wm, int wn, int tr, int tc,
                                           float C[2][4][4]) {
    #pragma unroll 4
    for (int ks = 0; ks < 16; ++ks) {
        uint32_t af[2][4], bf[4][2];
        #pragma unroll
        for (int mt = 0; mt < 2; ++mt) {
            const float* p = As + (wm * 32 + mt * 16 + tr) * LDA + ks * 8 + tc;
            af[mt][0] = __float_as_uint(p[0]);
            af[mt][1] = __float_as_uint(p[8 * LDA]);
            af[mt][2] = __float_as_uint(p[4]);
            af[mt][3] = __float_as_uint(p[8 * LDA + 4]);
        }
        #pragma unroll
        for (int nt = 0; nt < 4; ++nt) {
            const float* p = Bs + (wn * 32 + nt * 8 + tr) * LDA + ks * 8 + tc;
            bf[nt][0] = __float_as_uint(p[0]);
            bf[nt][1] = __float_as_uint(p[4]);
        }
        #pragma unroll
        for (int mt = 0; mt < 2; ++mt)
            #pragma unroll
            for (int nt = 0; nt < 4; ++nt)
                mma_tf32(C[mt][nt], af[mt], bf[nt]);
    }
}

// ---------------- standalone mean-aggregation gather ------------------------
// Warp per node: aggm[node] = mean_{j in in(node)} h[j]   (fp16 out, fp32 acc)
__global__ __launch_bounds__(256) void k_gather(
    const __half* __restrict__ hin, const int* __restrict__ srcs,
    const int* __restrict__ rowptr, __half* __restrict__ aggm, int n)
{
    const int lane = threadIdx.x & 31;
    const int node = blockIdx.x * 8 + (threadIdx.x >> 5);
    if (node >= n) return;
    const int beg = __ldg(&rowptr[node]);
    const int end = __ldg(&rowptr[node + 1]);
    float a0 = 0.f, a1 = 0.f, a2 = 0.f, a3 = 0.f;
    const uint2* hb = (const uint2*)hin;     // row stride = 32 uint2
    int e = beg;
    #pragma unroll 1
    for (; e + 4 <= end; e += 4) {
        int s0 = __ldg(&srcs[e + 0]);
        int s1 = __ldg(&srcs[e + 1]);
        int s2 = __ldg(&srcs[e + 2]);
        int s3 = __ldg(&srcs[e + 3]);
        uint2 u0 = __ldg(hb + (size_t)s0 * 32 + lane);
        uint2 u1 = __ldg(hb + (size_t)s1 * 32 + lane);
        uint2 u2 = __ldg(hb + (size_t)s2 * 32 + lane);
        uint2 u3 = __ldg(hb + (size_t)s3 * 32 + lane);
        float2 f;
        f = __half22float2(*(const __half2*)&u0.x); a0 += f.x; a1 += f.y;
        f = __half22float2(*(const __half2*)&u0.y); a2 += f.x; a3 += f.y;
        f = __half22float2(*(const __half2*)&u1.x); a0 += f.x; a1 += f.y;
        f = __half22float2(*(const __half2*)&u1.y); a2 += f.x; a3 += f.y;
        f = __half22float2(*(const __half2*)&u2.x); a0 += f.x; a1 += f.y;
        f = __half22float2(*(const __half2*)&u2.y); a2 += f.x; a3 += f.y;
        f = __half22float2(*(const __half2*)&u3.x); a0 += f.x; a1 += f.y;
        f = __half22float2(*(const __half2*)&u3.y); a2 += f.x; a3 += f.y;
    }
    for (; e < end; ++e) {
        uint2 u = __ldg(hb + (size_t)__ldg(&srcs[e]) * 32 + lane);
        float2 f;
        f = __half22float2(*(const __half2*)&u.x); a0 += f.x; a1 += f.y;
        f = __half22float2(*(const __half2*)&u.y); a2 += f.x; a3 += f.y;
    }
    const float inv = 1.0f / fmaxf((float)(end - beg), 1.0f);
    uint2 out;
    *(__half2*)&out.x = __floats2half2_rn(a0 * inv, a1 * inv);
    *(__half2*)&out.y = __floats2half2_rn(a2 * inv, a3 * inv);
    *((uint2*)(aggm + (size_t)node * 128) + lane) = out;
}

// ---------------- fused dual-GEMM layer on tf32 mma.sync --------------------
// CTA = 128-node tile; out = relu(aggm @ Wl + h @ Wr + bias).
// do_agg=0 -> embedding: input fp32 x, out = relu(x @ Wr + bias).
__global__ __launch_bounds__(512, 1) void k_sage_gemm(
    const __half* __restrict__ aggm, const void* __restrict__ hroot_v,
    const float* __restrict__ Wl, const float* __restrict__ bias,
    const float* __restrict__ Wr, __half* __restrict__ hout, int n, int do_agg)
{
    extern __shared__ float smem[];
    const int tid = threadIdx.x;
    const int wid = tid >> 5;
    const int lane = tid & 31;

    // pack B = Wl (or Wr for embedding): Bt[nn][k], tf32-rounded
    {
        const float* W0 = do_agg ? Wl : Wr;
        for (int idx = tid; idx < 16384; idx += 512) {
            int k = idx >> 7, nn = idx & 127;
            smem[F_B + nn * LDA + k] = __uint_as_float(f2tf32(W0[idx]));
        }
    }
    if (tid < 128) smem[F_BIAS + tid] = bias[tid];

    // load A tiles: warp owns 8 rows, lanes span 128 cols
    #pragma unroll
    for (int i = 0; i < 8; ++i) {
        const int row  = wid * 8 + i;
        const int node = blockIdx.x * 128 + row;
        float a0 = 0.f, a1 = 0.f, a2 = 0.f, a3 = 0.f;
        float r0 = 0.f, r1 = 0.f, r2 = 0.f, r3 = 0.f;
        if (node < n) {
            if (do_agg) {
                uint2 ua = __ldg((const uint2*)(aggm + (size_t)node * 128) + lane);
                uint2 uh = __ldg((const uint2*)((const __half*)hroot_v + (size_t)node * 128) + lane);
                float2 f;
                f = __half22float2(*(const __half2*)&ua.x); a0 = f.x; a1 = f.y;
                f = __half22float2(*(const __half2*)&ua.y); a2 = f.x; a3 = f.y;
                f = __half22float2(*(const __half2*)&uh.x); r0 = f.x; r1 = f.y;
                f = __half22float2(*(const __half2*)&uh.y); r2 = f.x; r3 = f.y;
            } else {
                const float4 v = __ldg((const float4*)hroot_v + (size_t)node * 32 + lane);
                r0 = v.x; r1 = v.y; r2 = v.z; r3 = v.w;
            }
        }
        float4 t1;
        t1.x = __uint_as_float(f2tf32(r0)); t1.y = __uint_as_float(f2tf32(r1));
        t1.z = __uint_as_float(f2tf32(r2)); t1.w = __uint_as_float(f2tf32(r3));
        *(float4*)(smem + F_A1 + row * LDA + 4 * lane) = t1;
        if (do_agg) {
            float4 t0;
            t0.x = __uint_as_float(f2tf32(a0)); t0.y = __uint_as_float(f2tf32(a1));
            t0.z = __uint_as_float(f2tf32(a2)); t0.w = __uint_as_float(f2tf32(a3));
            *(float4*)(smem + F_A0 + row * LDA + 4 * lane) = t0;
        }
    }
    __syncthreads();

    // GEMM: warp wid -> rows (wid&3)*32.., cols (wid>>2)*32..
    const int wm = wid & 3;
    const int wn = wid >> 2;
    const int tr = lane >> 2;
    const int tc = lane & 3;
    float C[2][4][4];
    #pragma unroll
    for (int mt = 0; mt < 2; ++mt)
        #pragma unroll
        for (int nt = 0; nt < 4; ++nt)
            #pragma unroll
            for (int q = 0; q < 4; ++q) C[mt][nt][q] = 0.f;

    if (do_agg) {
        gemm_accum(smem + F_A0, smem + F_B, wm, wn, tr, tc, C);   // agg @ Wl
        __syncthreads();
        for (int idx = tid; idx < 16384; idx += 512) {            // repack B=Wr
            int k = idx >> 7, nn = idx & 127;
            smem[F_B + nn * LDA + k] = __uint_as_float(f2tf32(Wr[idx]));
        }
        __syncthreads();
    }
    gemm_accum(smem + F_A1, smem + F_B, wm, wn, tr, tc, C);       // h @ Wr

    // epilogue: bias + relu -> fp16
    #pragma unroll
    for (int mt = 0; mt < 2; ++mt) {
        int r0i = wm * 32 + mt * 16 + tr;
        int nd0 = blockIdx.x * 128 + r0i;
        int nd1 = nd0 + 8;
        #pragma unroll
        for (int nt = 0; nt < 4; ++nt) {
            int col = wn * 32 + nt * 8 + tc * 2;
            float b0 = smem[F_BIAS + col], b1 = smem[F_BIAS + col + 1];
            if (nd0 < n) {
                __half2 v = __floats2half2_rn(fmaxf(C[mt][nt][0] + b0, 0.f),
                                              fmaxf(C[mt][nt][1] + b1, 0.f));
                *(__half2*)(hout + (size_t)nd0 * 128 + col) = v;
            }
            if (nd1 < n) {
                __half2 v = __floats2half2_rn(fmaxf(C[mt][nt][2] + b0, 0.f),
                                              fmaxf(C[mt][nt][3] + b1, 0.f));
                *(__half2*)(hout + (size_t)nd1 * 128 + col) = v;
            }
        }
    }
}

// ---------------- CSR build (3 kernels, no memset) ---------------------------
// invariant: g_counts is all-zero on entry to k_count (zero-init at load,
// re-zeroed by k_scan after reading). g_scan_flag zeroed by k_count.
__global__ void k_count(const int* __restrict__ ed, int* __restrict__ counts,
                        int* __restrict__ scan_flag, int E)
{
    int i = blockIdx.x * blockDim.x + threadIdx.x;
    if (i < 256) scan_flag[i] = 0;
    if (i < E) atomicAdd(&counts[ed[E + i]], 1);
}

// single-pass scan with chained block prefix (all blocks resident: NB<=148)
__global__ __launch_bounds__(1024) void k_scan(
    int* __restrict__ counts, int* __restrict__ rowptr, int* __restrict__ cursor,
    int* __restrict__ scan_val, int* __restrict__ scan_flag, int n)
{
    __shared__ int s[1024];
    __shared__ int sprefix;
    const int b = blockIdx.x;
    const int i = b * 1024 + threadIdx.x;
    const int v = (i < n) ? counts[i] : 0;
    s[threadIdx.x] = v;
    __syncthreads();
    #pragma unroll
    for (int off = 1; off < 1024; off <<= 1) {
        int t = (threadIdx.x >= off) ? s[threadIdx.x - off] : 0;
        __syncthreads();
        s[threadIdx.x] += t;
        __syncthreads();
    }
    const int total = s[1023];
    if (threadIdx.x == 0) {
        int p = 0;
        if (b > 0) {
            while (((volatile int*)scan_flag)[b - 1] == 0) {}
            __threadfence();
            p = ((volatile int*)scan_val)[b - 1];
        }
        scan_val[b] = p + total;
        __threadfence();
        ((volatile int*)scan_flag)[b] = 1;
        sprefix = p;
        if (b == gridDim.x - 1) rowptr[n] = p + total;
    }
    __syncthreads();
    if (i < n) {
        int rp = sprefix + s[threadIdx.x] - v;
        rowptr[i] = rp;
        cursor[i] = rp;
        counts[i] = 0;          // restore invariant for next use/replay
    }
}

__global__ void k_scatter(const int* __restrict__ ed, int* __restrict__ cursor,
                          int* __restrict__ srcs, int E)
{
    int i = blockIdx.x * blockDim.x + threadIdx.x;
    if (i < E) {
        int d = ed[E + i];
        int p = atomicAdd(&cursor[d], 1);
        srcs[p] = ed[i];
    }
}

// ---------------- attention combine (fp16 in, fp32 out) ---------------------
__global__ __launch_bounds__(256) void k_att(
    const __half* __restrict__ o0, const __half* __restrict__ o1,
    const float* __restrict__ watt, const float* __restrict__ batt,
    float4* __restrict__ agg, int n)
{
    const int lane = threadIdx.x & 31;
    const int gw = blockIdx.x * (blockDim.x >> 5) + (threadIdx.x >> 5);
    const int nw = gridDim.x * (blockDim.x >> 5);
    const int k0 = lane * 4;
    float wa0[4], wa1[4], wb0[4], wb1[4];
    #pragma unroll
    for (int c = 0; c < 4; ++c) {
        wa0[c] = __ldg(&watt[(k0 + c) * 2 + 0]);
        wa1[c] = __ldg(&watt[(k0 + c) * 2 + 1]);
        wb0[c] = __ldg(&watt[(128 + k0 + c) * 2 + 0]);
        wb1[c] = __ldg(&watt[(128 + k0 + c) * 2 + 1]);
    }
    const float bt0 = __ldg(&batt[0]), bt1 = __ldg(&batt[1]);

    for (int node = gw; node < n; node += nw) {
        uint2 ua = __ldg((const uint2*)(o0 + (size_t)node * 128) + lane);
        uint2 ub = __ldg((const uint2*)(o1 + (size_t)node * 128) + lane);
        float2 a01 = __half22float2(*(const __half2*)&ua.x);
        float2 a23 = __half22float2(*(const __half2*)&ua.y);
        float2 b01 = __half22float2(*(const __half2*)&ub.x);
        float2 b23 = __half22float2(*(const __half2*)&ub.y);
        float p0 = a01.x * wa0[0] + a01.y * wa0[1] + a23.x * wa0[2] + a23.y * wa0[3]
                 + b01.x * wb0[0] + b01.y * wb0[1] + b23.x * wb0[2] + b23.y * wb0[3];
        float p1 = a01.x * wa1[0] + a01.y * wa1[1] + a23.x * wa1[2] + a23.y * wa1[3]
                 + b01.x * wb1[0] + b01.y * wb1[1] + b23.x * wb1[2] + b23.y * wb1[3];
        #pragma unroll
        for (int off = 16; off; off >>= 1) {
            p0 += __shfl_xor_sync(FULLMASK, p0, off);
            p1 += __shfl_xor_sync(FULLMASK, p1, off);
        }
        float z0 = p0 + bt0, z1 = p1 + bt1;
        float m = fmaxf(z0, z1);
        float e0 = expf(z0 - m), e1 = expf(z1 - m);
        float inv = 1.0f / (e0 + e1);
        float w0 = e0 * inv, w1 = e1 * inv;
        float4 rr;
        rr.x = w0 * a01.x + w1 * b01.x;
        rr.y = w0 * a01.y + w1 * b01.y;
        rr.z = w0 * a23.x + w1 * b23.x;
        rr.w = w0 * a23.y + w1 * b23.y;
        agg[node * 32 + lane] = rr;
    }
}

// ---------------- classifier + pattern heads -------------------------------
__global__ __launch_bounds__(256) void k_heads(
    const float4* __restrict__ agg,
    const float* __restrict__ wc1, const float* __restrict__ bc1,
    const float* __restrict__ wc2, const float* __restrict__ bc2,
    const float* __restrict__ wp1, const float* __restrict__ bp1,
    const float* __restrict__ wp2, const float* __restrict__ bp2,
    float* __restrict__ fraud, float* __restrict__ pat, int n)
{
    extern __shared__ float sm[];
    float* sC1 = sm;
    float* sP1 = sC1 + 8192;
    float* sC2 = sP1 + 8192;
    float* sP2 = sC2 + 128;
    float* sBC1 = sP2 + 320;
    float* sBP1 = sBC1 + 64;
    float* sBC2 = sBP1 + 64;
    float* sBP2 = sBC2 + 2;
    for (int i = threadIdx.x; i < 8192; i += blockDim.x) { sC1[i] = wc1[i]; sP1[i] = wp1[i]; }
    for (int i = threadIdx.x; i < 128;  i += blockDim.x) sC2[i] = wc2[i];
    for (int i = threadIdx.x; i < 320;  i += blockDim.x) sP2[i] = wp2[i];
    for (int i = threadIdx.x; i < 64;   i += blockDim.x) { sBC1[i] = bc1[i]; sBP1[i] = bp1[i]; }
    if (threadIdx.x < 2) sBC2[threadIdx.x] = bc2[threadIdx.x];
    if (threadIdx.x < 5) sBP2[threadIdx.x] = bp2[threadIdx.x];
    __syncthreads();

    const int lane = threadIdx.x & 31;
    const int gw = blockIdx.x * (blockDim.x >> 5) + (threadIdx.x >> 5);
    const int nw = gridDim.x * (blockDim.x >> 5);
    const float2* sC1v = (const float2*)sC1;
    const float2* sP1v = (const float2*)sP1;

    const int hA = 2 * lane, hBb = 2 * lane + 1;
    const float c2a0 = sC2[hA * 2 + 0], c2a1 = sC2[hA * 2 + 1];
    const float c2b0 = sC2[hBb * 2 + 0], c2b1 = sC2[hBb * 2 + 1];
    float p2a[5], p2b[5];
    #pragma unroll
    for (int j = 0; j < 5; ++j) { p2a[j] = sP2[hA * 5 + j]; p2b[j] = sP2[hBb * 5 + j]; }
    const float bC1a = sBC1[hA], bC1b = sBC1[hBb];
    const float bP1a = sBP1[hA], bP1b = sBP1[hBb];
    const float bC2_0 = sBC2[0], bC2_1 = sBC2[1];
    float bP2v[5];
    #pragma unroll
    for (int j = 0; j < 5; ++j) bP2v[j] = sBP2[j];

    for (int node = gw; node < n; node += nw) {
        float4 ar = agg[node * 32 + lane];
        float hc0 = bC1a, hc1 = bC1b, hp0 = bP1a, hp1 = bP1b;
        #pragma unroll 4
        for (int kk = 0; kk < 32; ++kk) {
            float av[4];
            av[0] = __shfl_sync(FULLMASK, ar.x, kk);
            av[1] = __shfl_sync(FULLMASK, ar.y, kk);
            av[2] = __shfl_sync(FULLMASK, ar.z, kk);
            av[3] = __shfl_sync(FULLMASK, ar.w, kk);
            #pragma unroll
            for (int j = 0; j < 4; ++j) {
                int k = kk * 4 + j;
                float2 wc = sC1v[k * 32 + lane];
                float2 wp = sP1v[k * 32 + lane];
                hc0 += av[j] * wc.x; hc1 += av[j] * wc.y;
                hp0 += av[j] * wp.x; hp1 += av[j] * wp.y;
            }
        }
        hc0 = fmaxf(hc0, 0.f); hc1 = fmaxf(hc1, 0.f);
        hp0 = fmaxf(hp0, 0.f); hp1 = fmaxf(hp1, 0.f);

        float f0 = hc0 * c2a0 + hc1 * c2b0;
        float f1 = hc0 * c2a1 + hc1 * c2b1;
        float q[5];
        #pragma unroll
        for (int j = 0; j < 5; ++j) q[j] = hp0 * p2a[j] + hp1 * p2b[j];
        #pragma unroll
        for (int off = 16; off; off >>= 1) {
            f0 += __shfl_xor_sync(FULLMASK, f0, off);
            f1 += __shfl_xor_sync(FULLMASK, f1, off);
            #pragma unroll
            for (int j = 0; j < 5; ++j) q[j] += __shfl_xor_sync(FULLMASK, q[j], off);
        }
        if (lane == 0) {
            fraud[node * 2 + 0] = f0 + bC2_0;
            fraud[node * 2 + 1] = f1 + bC2_1;
            #pragma unroll
            for (int j = 0; j < 5; ++j) pat[node * 5 + j] = q[j] + bP2v[j];
        }
    }
}

// ---------------- launcher --------------------------------------------------
extern "C" void kernel_launch(void* const* d_in, const int* in_sizes, int n_in,
                              void* d_out, int out_size)
{
    const float* x     = (const float*)d_in[0];
    const int*   e0    = (const int*)  d_in[1];
    const int*   e1    = (const int*)  d_in[2];
    const float* w_emb = (const float*)d_in[3];
    const float* b_emb = (const float*)d_in[4];
    const float* Wl    = (const float*)d_in[5];
    const float* bl    = (const float*)d_in[6];
    const float* Wr    = (const float*)d_in[7];
    const float* w_att = (const float*)d_in[8];
    const float* b_att = (const float*)d_in[9];
    const float* w_c1  = (const float*)d_in[10];
    const float* b_c1  = (const float*)d_in[11];
    const float* w_c2  = (const float*)d_in[12];
    const float* b_c2  = (const float*)d_in[13];
    const float* w_p1  = (const float*)d_in[14];
    const float* b_p1  = (const float*)d_in[15];
    const float* w_p2  = (const float*)d_in[16];
    const float* b_p2  = (const float*)d_in[17];

    int n = in_sizes[0] / 128; if (n > NMAX) n = NMAX;
    int E = in_sizes[1] / 2;   if (E > EMAX) E = EMAX;

    float* out_fraud = (float*)d_out;
    float* out_pat   = out_fraud + (size_t)n * 2;
    float* out_agg   = out_pat   + (size_t)n * 5;

    __half *h0, *hA, *hB, *o0, *o1, *aggm;
    int *counts, *rowptr, *cursor, *srcs, *sval, *sflag;
    cudaGetSymbolAddress((void**)&h0, g_h0);
    cudaGetSymbolAddress((void**)&hA, g_hA);
    cudaGetSymbolAddress((void**)&hB, g_hB);
    cudaGetSymbolAddress((void**)&o0, g_o0);
    cudaGetSymbolAddress((void**)&o1, g_o1);
    cudaGetSymbolAddress((void**)&aggm, g_agg);
    cudaGetSymbolAddress((void**)&counts, g_counts);
    cudaGetSymbolAddress((void**)&rowptr, g_rowptr);
    cudaGetSymbolAddress((void**)&cursor, g_cursor);
    cudaGetSymbolAddress((void**)&srcs, g_srcs);
    cudaGetSymbolAddress((void**)&sval, g_scan_val);
    cudaGetSymbolAddress((void**)&sflag, g_scan_flag);

    const int SM_HEADS = (8192 + 8192 + 128 + 320 + 64 + 64 + 2 + 5) * 4;
    cudaFuncSetAttribute(k_sage_gemm, cudaFuncAttributeMaxDynamicSharedMemorySize, SMEM_TC);
    cudaFuncSetAttribute(k_heads,     cudaFuncAttributeMaxDynamicSharedMemorySize, SM_HEADS);

    const int tiles = (n + 127) / 128;
    const int NB = (n + 1023) / 1024;           // 98 blocks -> all resident

    // node embedding: relu(x @ w_emb + b_emb)
    k_sage_gemm<<<tiles, 512, SMEM_TC>>>(nullptr, x, nullptr, b_emb, w_emb, h0, n, 0);

    for (int et = 0; et < 2; ++et) {
        const int* ed = et ? e1 : e0;
        k_count<<<(E + 255) / 256, 256>>>(ed, counts, sflag, E);
        k_scan<<<NB, 1024>>>(counts, rowptr, cursor, sval, sflag, n);
        k_scatter<<<(E + 255) / 256, 256>>>(ed, cursor, srcs, E);

        const __half* hin = h0;
        __half* outs[3] = { hA, hB, et ? o1 : o0 };
        for (int l = 0; l < 3; ++l) {
            const float* Wlp = Wl + (size_t)(et * 3 + l) * 128 * 128;
            const float* blp = bl + (size_t)(et * 3 + l) * 128;
            const float* Wrp = Wr + (size_t)(et * 3 + l) * 128 * 128;
            k_gather<<<(n + 7) / 8, 256>>>(hin, srcs, rowptr, aggm, n);
            k_sage_gemm<<<tiles, 512, SMEM_TC>>>(aggm, hin, Wlp, blp, Wrp, outs[l], n, 1);
            hin = outs[l];
        }
    }

    k_att<<<1024, 256>>>(o0, o1, w_att, b_att, (float4*)out_agg, n);
    k_heads<<<592, 256, SM_HEADS>>>((const float4*)out_agg,
                                    w_c1, b_c1, w_c2, b_c2,
                                    w_p1, b_p1, w_p2, b_p2,
                                    out_fraud, out_pat, n);
}

// round 8
// speedup vs baseline: 2.2387x; 1.2633x over previous
#include <cuda_runtime.h>
#include <cuda_fp16.h>
#include <cstdint>

#define NMAX 100000
#define EMAX 1600000
#define FULLMASK 0xffffffffu

// ---------------- scratch (static device allocations; no cudaMalloc) -------
__device__ __half g_h0[NMAX * 128];
__device__ __half g_hA[NMAX * 128];
__device__ __half g_hB[NMAX * 128];
__device__ __half g_o0[NMAX * 128];
__device__ __half g_o1[NMAX * 128];
__device__ __half g_agg[NMAX * 128];
__device__ __half g_pw[7 * 128 * 256];      // packed fp16 weights [g][nn][k]
__device__ int    g_counts[NMAX];
__device__ int    g_rowptr[NMAX + 1];
__device__ int    g_cursor[NMAX];
__device__ int    g_srcs[EMAX];
__device__ int    g_scan_val[256];
__device__ int    g_scan_flag[256];

// mma.sync m16n8k16 f16 -> f32 accum (portable, sm_80+)
__device__ __forceinline__ void mma_f16(float* d, const uint32_t* a, const uint32_t* b) {
    asm volatile(
        "mma.sync.aligned.m16n8k16.row.col.f32.f16.f16.f32 "
        "{%0,%1,%2,%3}, {%4,%5,%6,%7}, {%8,%9}, {%0,%1,%2,%3};"
        : "+f"(d[0]), "+f"(d[1]), "+f"(d[2]), "+f"(d[3])
        : "r"(a[0]), "r"(a[1]), "r"(a[2]), "r"(a[3]), "r"(b[0]), "r"(b[1]));
}

// smem geometry (halves): A[128][264] | B[128][264] | bias[128]f32
static constexpr int LDAH   = 264;
static constexpr int SMEM_GEMM = (2 * 128 * LDAH) * 2 + 128 * 4;   // 136192 B

// ---------------- weight pre-pack: fp32 [k][nn] -> fp16 [g][nn][k] ----------
// g = 0..5: sage (k<128 -> Wl[g], else Wr[g]); g = 6: embedding (k<128 w_emb, else 0)
__global__ void k_pack(const float* __restrict__ Wl, const float* __restrict__ Wr,
                       const float* __restrict__ w_emb, __half* __restrict__ pw)
{
    __shared__ float tile[32][33];
    const int g = blockIdx.z, k0 = blockIdx.x * 32, n0 = blockIdx.y * 32;
    const int tx = threadIdx.x, ty = threadIdx.y;
    #pragma unroll
    for (int i = 0; i < 4; ++i) {
        int k = k0 + ty + 8 * i, nn = n0 + tx;
        float v;
        if (g < 6) v = (k < 128) ? Wl[((size_t)g * 128 + k) * 128 + nn]
                                 : Wr[((size_t)g * 128 + (k - 128)) * 128 + nn];
        else       v = (k < 128) ? w_emb[(size_t)k * 128 + nn] : 0.f;
        tile[ty + 8 * i][tx] = v;
    }
    __syncthreads();
    #pragma unroll
    for (int i = 0; i < 4; ++i) {
        int k = k0 + tx, nn = n0 + ty + 8 * i;
        pw[((size_t)g * 128 + nn) * 256 + k] = __float2half_rn(tile[tx][ty + 8 * i]);
    }
}

// ---------------- standalone mean-aggregation gather ------------------------
// Warp per node: aggm[node] = mean_{j in in(node)} h[j]   (fp16 out, fp32 acc)
__global__ __launch_bounds__(256) void k_gather(
    const __half* __restrict__ hin, const int* __restrict__ srcs,
    const int* __restrict__ rowptr, __half* __restrict__ aggm, int n)
{
    const int lane = threadIdx.x & 31;
    const int node = blockIdx.x * 8 + (threadIdx.x >> 5);
    if (node >= n) return;
    const int beg = __ldg(&rowptr[node]);
    const int end = __ldg(&rowptr[node + 1]);
    float a0 = 0.f, a1 = 0.f, a2 = 0.f, a3 = 0.f;
    const uint2* hb = (const uint2*)hin;     // row stride = 32 uint2
    int e = beg;
    #pragma unroll 1
    for (; e + 4 <= end; e += 4) {
        int s0 = __ldg(&srcs[e + 0]);
        int s1 = __ldg(&srcs[e + 1]);
        int s2 = __ldg(&srcs[e + 2]);
        int s3 = __ldg(&srcs[e + 3]);
        uint2 u0 = __ldg(hb + (size_t)s0 * 32 + lane);
        uint2 u1 = __ldg(hb + (size_t)s1 * 32 + lane);
        uint2 u2 = __ldg(hb + (size_t)s2 * 32 + lane);
        uint2 u3 = __ldg(hb + (size_t)s3 * 32 + lane);
        float2 f;
        f = __half22float2(*(const __half2*)&u0.x); a0 += f.x; a1 += f.y;
        f = __half22float2(*(const __half2*)&u0.y); a2 += f.x; a3 += f.y;
        f = __half22float2(*(const __half2*)&u1.x); a0 += f.x; a1 += f.y;
        f = __half22float2(*(const __half2*)&u1.y); a2 += f.x; a3 += f.y;
        f = __half22float2(*(const __half2*)&u2.x); a0 += f.x; a1 += f.y;
        f = __half22float2(*(const __half2*)&u2.y); a2 += f.x; a3 += f.y;
        f = __half22float2(*(const __half2*)&u3.x); a0 += f.x; a1 += f.y;
        f = __half22float2(*(const __half2*)&u3.y); a2 += f.x; a3 += f.y;
    }
    for (; e < end; ++e) {
        uint2 u = __ldg(hb + (size_t)__ldg(&srcs[e]) * 32 + lane);
        float2 f;
        f = __half22float2(*(const __half2*)&u.x); a0 += f.x; a1 += f.y;
        f = __half22float2(*(const __half2*)&u.y); a2 += f.x; a3 += f.y;
    }
    const float inv = 1.0f / fmaxf((float)(end - beg), 1.0f);
    uint2 out;
    *(__half2*)&out.x = __floats2half2_rn(a0 * inv, a1 * inv);
    *(__half2*)&out.y = __floats2half2_rn(a2 * inv, a3 * inv);
    *((uint2*)(aggm + (size_t)node * 128) + lane) = out;
}

// ---------------- single fused K=256 GEMM layer (fp16 MMA) ------------------
// CTA = 128-node tile; out = relu([aggm|h] @ pwg^T + bias), pwg = [nn][k] fp16.
// do_agg=0 -> embedding: A = [x_fp16 | 0], pwg upper-k half is zero.
__global__ __launch_bounds__(512, 1) void k_sage_gemm(
    const __half* __restrict__ aggm, const void* __restrict__ hroot_v,
    const __half* __restrict__ pwg, const float* __restrict__ bias,
    __half* __restrict__ hout, int n, int do_agg)
{
    extern __shared__ __align__(16) char smem_raw[];
    __half* sA = (__half*)smem_raw;                 // [128][264]
    __half* sB = sA + 128 * LDAH;                   // [128][264]
    float*  sBias = (float*)(sB + 128 * LDAH);      // [128]
    const int tid = threadIdx.x;
    const int wid = tid >> 5;
    const int lane = tid & 31;

    // B copy: coalesced uint4, 128 rows x 32 chunks
    {
        const uint4* pw4 = (const uint4*)pwg;
        #pragma unroll
        for (int i = tid; i < 4096; i += 512) {
            int row = i >> 5, c = i & 31;
            ((uint4*)(sB + row * LDAH))[c] = __ldg(pw4 + i);
        }
    }
    if (tid < 128) sBias[tid] = bias[tid];

    // A staging: warp owns 8 rows; lanes span cols (4 halves each half-row)
    #pragma unroll
    for (int i = 0; i < 8; ++i) {
        const int row  = wid * 8 + i;
        const int node = blockIdx.x * 128 + row;
        uint2 ua = make_uint2(0u, 0u), uh = make_uint2(0u, 0u);
        if (node < n) {
            if (do_agg) {
                ua = __ldg((const uint2*)(aggm + (size_t)node * 128) + lane);
                uh = __ldg((const uint2*)((const __half*)hroot_v + (size_t)node * 128) + lane);
            } else {
                const float4 v = __ldg((const float4*)hroot_v + (size_t)node * 32 + lane);
                *(__half2*)&ua.x = __floats2half2_rn(v.x, v.y);
                *(__half2*)&ua.y = __floats2half2_rn(v.z, v.w);
            }
        }
        ((uint2*)(sA + row * LDAH))[lane] = ua;          // cols 0..127
        ((uint2*)(sA + row * LDAH + 128))[lane] = uh;    // cols 128..255
    }
    __syncthreads();

    // GEMM: warp wid -> rows (wid&3)*32.., cols (wid>>2)*32..; K=256, 16 ksteps
    const int wm = wid & 3;
    const int wn = wid >> 2;
    const int tr = lane >> 2;
    const int tc = lane & 3;
    float C[2][4][4];
    #pragma unroll
    for (int mt = 0; mt < 2; ++mt)
        #pragma unroll
        for (int nt = 0; nt < 4; ++nt)
            #pragma unroll
            for (int q = 0; q < 4; ++q) C[mt][nt][q] = 0.f;

    #pragma unroll 4
    for (int ks = 0; ks < 16; ++ks) {
        const int kb = ks * 16 + 2 * tc;
        uint32_t af[2][4], bf[4][2];
        #pragma unroll
        for (int mt = 0; mt < 2; ++mt) {
            const __half* p = sA + (wm * 32 + mt * 16 + tr) * LDAH + kb;
            af[mt][0] = *(const uint32_t*)(p);
            af[mt][1] = *(const uint32_t*)(p + 8 * LDAH);
            af[mt][2] = *(const uint32_t*)(p + 8);
            af[mt][3] = *(const uint32_t*)(p + 8 * LDAH + 8);
        }
        #pragma unroll
        for (int nt = 0; nt < 4; ++nt) {
            const __half* p = sB + (wn * 32 + nt * 8 + tr) * LDAH + kb;
            bf[nt][0] = *(const uint32_t*)(p);
            bf[nt][1] = *(const uint32_t*)(p + 8);
        }
        #pragma unroll
        for (int mt = 0; mt < 2; ++mt)
            #pragma unroll
            for (int nt = 0; nt < 4; ++nt)
                mma_f16(C[mt][nt], af[mt], bf[nt]);
    }

    // epilogue: bias + relu -> fp16
    #pragma unroll
    for (int mt = 0; mt < 2; ++mt) {
        int r0i = wm * 32 + mt * 16 + tr;
        int nd0 = blockIdx.x * 128 + r0i;
        int nd1 = nd0 + 8;
        #pragma unroll
        for (int nt = 0; nt < 4; ++nt) {
            int col = wn * 32 + nt * 8 + tc * 2;
            float b0 = sBias[col], b1 = sBias[col + 1];
            if (nd0 < n) {
                __half2 v = __floats2half2_rn(fmaxf(C[mt][nt][0] + b0, 0.f),
                                              fmaxf(C[mt][nt][1] + b1, 0.f));
                *(__half2*)(hout + (size_t)nd0 * 128 + col) = v;
            }
            if (nd1 < n) {
                __half2 v = __floats2half2_rn(fmaxf(C[mt][nt][2] + b0, 0.f),
                                              fmaxf(C[mt][nt][3] + b1, 0.f));
                *(__half2*)(hout + (size_t)nd1 * 128 + col) = v;
            }
        }
    }
}

// ---------------- CSR build (3 kernels, no memset) ---------------------------
__global__ void k_count(const int* __restrict__ ed, int* __restrict__ counts,
                        int* __restrict__ scan_flag, int E)
{
    int i = blockIdx.x * blockDim.x + threadIdx.x;
    if (i < 256) scan_flag[i] = 0;
    if (i < E) atomicAdd(&counts[ed[E + i]], 1);
}

__global__ __launch_bounds__(1024) void k_scan(
    int* __restrict__ counts, int* __restrict__ rowptr, int* __restrict__ cursor,
    int* __restrict__ scan_val, int* __restrict__ scan_flag, int n)
{
    __shared__ int s[1024];
    __shared__ int sprefix;
    const int b = blockIdx.x;
    const int i = b * 1024 + threadIdx.x;
    const int v = (i < n) ? counts[i] : 0;
    s[threadIdx.x] = v;
    __syncthreads();
    #pragma unroll
    for (int off = 1; off < 1024; off <<= 1) {
        int t = (threadIdx.x >= off) ? s[threadIdx.x - off] : 0;
        __syncthreads();
        s[threadIdx.x] += t;
        __syncthreads();
    }
    const int total = s[1023];
    if (threadIdx.x == 0) {
        int p = 0;
        if (b > 0) {
            while (((volatile int*)scan_flag)[b - 1] == 0) {}
            __threadfence();
            p = ((volatile int*)scan_val)[b - 1];
        }
        scan_val[b] = p + total;
        __threadfence();
        ((volatile int*)scan_flag)[b] = 1;
        sprefix = p;
        if (b == gridDim.x - 1) rowptr[n] = p + total;
    }
    __syncthreads();
    if (i < n) {
        int rp = sprefix + s[threadIdx.x] - v;
        rowptr[i] = rp;
        cursor[i] = rp;
        counts[i] = 0;          // restore invariant for next use/replay
    }
}

__global__ void k_scatter(const int* __restrict__ ed, int* __restrict__ cursor,
                          int* __restrict__ srcs, int E)
{
    int i = blockIdx.x * blockDim.x + threadIdx.x;
    if (i < E) {
        int d = ed[E + i];
        int p = atomicAdd(&cursor[d], 1);
        srcs[p] = ed[i];
    }
}

// ---------------- attention combine (fp16 in, fp32 out) ---------------------
__global__ __launch_bounds__(256) void k_att(
    const __half* __restrict__ o0, const __half* __restrict__ o1,
    const float* __restrict__ watt, const float* __restrict__ batt,
    float4* __restrict__ agg, int n)
{
    const int lane = threadIdx.x & 31;
    const int gw = blockIdx.x * (blockDim.x >> 5) + (threadIdx.x >> 5);
    const int nw = gridDim.x * (blockDim.x >> 5);
    const int k0 = lane * 4;
    float wa0[4], wa1[4], wb0[4], wb1[4];
    #pragma unroll
    for (int c = 0; c < 4; ++c) {
        wa0[c] = __ldg(&watt[(k0 + c) * 2 + 0]);
        wa1[c] = __ldg(&watt[(k0 + c) * 2 + 1]);
        wb0[c] = __ldg(&watt[(128 + k0 + c) * 2 + 0]);
        wb1[c] = __ldg(&watt[(128 + k0 + c) * 2 + 1]);
    }
    const float bt0 = __ldg(&batt[0]), bt1 = __ldg(&batt[1]);

    for (int node = gw; node < n; node += nw) {
        uint2 ua = __ldg((const uint2*)(o0 + (size_t)node * 128) + lane);
        uint2 ub = __ldg((const uint2*)(o1 + (size_t)node * 128) + lane);
        float2 a01 = __half22float2(*(const __half2*)&ua.x);
        float2 a23 = __half22float2(*(const __half2*)&ua.y);
        float2 b01 = __half22float2(*(const __half2*)&ub.x);
        float2 b23 = __half22float2(*(const __half2*)&ub.y);
        float p0 = a01.x * wa0[0] + a01.y * wa0[1] + a23.x * wa0[2] + a23.y * wa0[3]
                 + b01.x * wb0[0] + b01.y * wb0[1] + b23.x * wb0[2] + b23.y * wb0[3];
        float p1 = a01.x * wa1[0] + a01.y * wa1[1] + a23.x * wa1[2] + a23.y * wa1[3]
                 + b01.x * wb1[0] + b01.y * wb1[1] + b23.x * wb1[2] + b23.y * wb1[3];
        #pragma unroll
        for (int off = 16; off; off >>= 1) {
            p0 += __shfl_xor_sync(FULLMASK, p0, off);
            p1 += __shfl_xor_sync(FULLMASK, p1, off);
        }
        float z0 = p0 + bt0, z1 = p1 + bt1;
        float m = fmaxf(z0, z1);
        float e0 = expf(z0 - m), e1 = expf(z1 - m);
        float inv = 1.0f / (e0 + e1);
        float w0 = e0 * inv, w1 = e1 * inv;
        float4 rr;
        rr.x = w0 * a01.x + w1 * b01.x;
        rr.y = w0 * a01.y + w1 * b01.y;
        rr.z = w0 * a23.x + w1 * b23.x;
        rr.w = w0 * a23.y + w1 * b23.y;
        agg[node * 32 + lane] = rr;
    }
}

// ---------------- classifier + pattern heads -------------------------------
__global__ __launch_bounds__(256) void k_heads(
    const float4* __restrict__ agg,
    const float* __restrict__ wc1, const float* __restrict__ bc1,
    const float* __restrict__ wc2, const float* __restrict__ bc2,
    const float* __restrict__ wp1, const float* __restrict__ bp1,
    const float* __restrict__ wp2, const float* __restrict__ bp2,
    float* __restrict__ fraud, float* __restrict__ pat, int n)
{
    extern __shared__ float sm[];
    float* sC1 = sm;
    float* sP1 = sC1 + 8192;
    float* sC2 = sP1 + 8192;
    float* sP2 = sC2 + 128;
    float* sBC1 = sP2 + 320;
    float* sBP1 = sBC1 + 64;
    float* sBC2 = sBP1 + 64;
    float* sBP2 = sBC2 + 2;
    for (int i = threadIdx.x; i < 8192; i += blockDim.x) { sC1[i] = wc1[i]; sP1[i] = wp1[i]; }
    for (int i = threadIdx.x; i < 128;  i += blockDim.x) sC2[i] = wc2[i];
    for (int i = threadIdx.x; i < 320;  i += blockDim.x) sP2[i] = wp2[i];
    for (int i = threadIdx.x; i < 64;   i += blockDim.x) { sBC1[i] = bc1[i]; sBP1[i] = bp1[i]; }
    if (threadIdx.x < 2) sBC2[threadIdx.x] = bc2[threadIdx.x];
    if (threadIdx.x < 5) sBP2[threadIdx.x] = bp2[threadIdx.x];
    __syncthreads();

    const int lane = threadIdx.x & 31;
    const int gw = blockIdx.x * (blockDim.x >> 5) + (threadIdx.x >> 5);
    const int nw = gridDim.x * (blockDim.x >> 5);
    const float2* sC1v = (const float2*)sC1;
    const float2* sP1v = (const float2*)sP1;

    const int hA = 2 * lane, hBb = 2 * lane + 1;
    const float c2a0 = sC2[hA * 2 + 0], c2a1 = sC2[hA * 2 + 1];
    const float c2b0 = sC2[hBb * 2 + 0], c2b1 = sC2[hBb * 2 + 1];
    float p2a[5], p2b[5];
    #pragma unroll
    for (int j = 0; j < 5; ++j) { p2a[j] = sP2[hA * 5 + j]; p2b[j] = sP2[hBb * 5 + j]; }
    const float bC1a = sBC1[hA], bC1b = sBC1[hBb];
    const float bP1a = sBP1[hA], bP1b = sBP1[hBb];
    const float bC2_0 = sBC2[0], bC2_1 = sBC2[1];
    float bP2v[5];
    #pragma unroll
    for (int j = 0; j < 5; ++j) bP2v[j] = sBP2[j];

    for (int node = gw; node < n; node += nw) {
        float4 ar = agg[node * 32 + lane];
        float hc0 = bC1a, hc1 = bC1b, hp0 = bP1a, hp1 = bP1b;
        #pragma unroll 4
        for (int kk = 0; kk < 32; ++kk) {
            float av[4];
            av[0] = __shfl_sync(FULLMASK, ar.x, kk);
            av[1] = __shfl_sync(FULLMASK, ar.y, kk);
            av[2] = __shfl_sync(FULLMASK, ar.z, kk);
            av[3] = __shfl_sync(FULLMASK, ar.w, kk);
            #pragma unroll
            for (int j = 0; j < 4; ++j) {
                int k = kk * 4 + j;
                float2 wc = sC1v[k * 32 + lane];
                float2 wp = sP1v[k * 32 + lane];
                hc0 += av[j] * wc.x; hc1 += av[j] * wc.y;
                hp0 += av[j] * wp.x; hp1 += av[j] * wp.y;
            }
        }
        hc0 = fmaxf(hc0, 0.f); hc1 = fmaxf(hc1, 0.f);
        hp0 = fmaxf(hp0, 0.f); hp1 = fmaxf(hp1, 0.f);

        float f0 = hc0 * c2a0 + hc1 * c2b0;
        float f1 = hc0 * c2a1 + hc1 * c2b1;
        float q[5];
        #pragma unroll
        for (int j = 0; j < 5; ++j) q[j] = hp0 * p2a[j] + hp1 * p2b[j];
        #pragma unroll
        for (int off = 16; off; off >>= 1) {
            f0 += __shfl_xor_sync(FULLMASK, f0, off);
            f1 += __shfl_xor_sync(FULLMASK, f1, off);
            #pragma unroll
            for (int j = 0; j < 5; ++j) q[j] += __shfl_xor_sync(FULLMASK, q[j], off);
        }
        if (lane == 0) {
            fraud[node * 2 + 0] = f0 + bC2_0;
            fraud[node * 2 + 1] = f1 + bC2_1;
            #pragma unroll
            for (int j = 0; j < 5; ++j) pat[node * 5 + j] = q[j] + bP2v[j];
        }
    }
}

// ---------------- launcher --------------------------------------------------
extern "C" void kernel_launch(void* const* d_in, const int* in_sizes, int n_in,
                              void* d_out, int out_size)
{
    const float* x     = (const float*)d_in[0];
    const int*   e0    = (const int*)  d_in[1];
    const int*   e1    = (const int*)  d_in[2];
    const float* w_emb = (const float*)d_in[3];
    const float* b_emb = (const float*)d_in[4];
    const float* Wl    = (const float*)d_in[5];
    const float* bl    = (const float*)d_in[6];
    const float* Wr    = (const float*)d_in[7];
    const float* w_att = (const float*)d_in[8];
    const float* b_att = (const float*)d_in[9];
    const float* w_c1  = (const float*)d_in[10];
    const float* b_c1  = (const float*)d_in[11];
    const float* w_c2  = (const float*)d_in[12];
    const float* b_c2  = (const float*)d_in[13];
    const float* w_p1  = (const float*)d_in[14];
    const float* b_p1  = (const float*)d_in[15];
    const float* w_p2  = (const float*)d_in[16];
    const float* b_p2  = (const float*)d_in[17];

    int n = in_sizes[0] / 128; if (n > NMAX) n = NMAX;
    int E = in_sizes[1] / 2;   if (E > EMAX) E = EMAX;

    float* out_fraud = (float*)d_out;
    float* out_pat   = out_fraud + (size_t)n * 2;
    float* out_agg   = out_pat   + (size_t)n * 5;

    __half *h0, *hA, *hB, *o0, *o1, *aggm, *pw;
    int *counts, *rowptr, *cursor, *srcs, *sval, *sflag;
    cudaGetSymbolAddress((void**)&h0, g_h0);
    cudaGetSymbolAddress((void**)&hA, g_hA);
    cudaGetSymbolAddress((void**)&hB, g_hB);
    cudaGetSymbolAddress((void**)&o0, g_o0);
    cudaGetSymbolAddress((void**)&o1, g_o1);
    cudaGetSymbolAddress((void**)&aggm, g_agg);
    cudaGetSymbolAddress((void**)&pw, g_pw);
    cudaGetSymbolAddress((void**)&counts, g_counts);
    cudaGetSymbolAddress((void**)&rowptr, g_rowptr);
    cudaGetSymbolAddress((void**)&cursor, g_cursor);
    cudaGetSymbolAddress((void**)&srcs, g_srcs);
    cudaGetSymbolAddress((void**)&sval, g_scan_val);
    cudaGetSymbolAddress((void**)&sflag, g_scan_flag);

    const int SM_HEADS = (8192 + 8192 + 128 + 320 + 64 + 64 + 2 + 5) * 4;
    cudaFuncSetAttribute(k_sage_gemm, cudaFuncAttributeMaxDynamicSharedMemorySize, SMEM_GEMM);
    cudaFuncSetAttribute(k_heads,     cudaFuncAttributeMaxDynamicSharedMemorySize, SM_HEADS);

    const int tiles = (n + 127) / 128;
    const int NB = (n + 1023) / 1024;           // <=98 blocks -> all resident

    // pack all weights (6 sage pairs + embedding) into fp16 [nn][k]
    k_pack<<<dim3(8, 4, 7), dim3(32, 8)>>>(Wl, Wr, w_emb, pw);

    // node embedding: relu(x @ w_emb + b_emb)
    k_sage_gemm<<<tiles, 512, SMEM_GEMM>>>(nullptr, x, pw + 6 * 32768, b_emb, h0, n, 0);

    for (int et = 0; et < 2; ++et) {
        const int* ed = et ? e1 : e0;
        k_count<<<(E + 255) / 256, 256>>>(ed, counts, sflag, E);
        k_scan<<<NB, 1024>>>(counts, rowptr, cursor, sval, sflag, n);
        k_scatter<<<(E + 255) / 256, 256>>>(ed, cursor, srcs, E);

        const __half* hin = h0;
        __half* outs[3] = { hA, hB, et ? o1 : o0 };
        for (int l = 0; l < 3; ++l) {
            const __half* pwg = pw + (size_t)(et * 3 + l) * 32768;
            const float* blp = bl + (size_t)(et * 3 + l) * 128;
            k_gather<<<(n + 7) / 8, 256>>>(hin, srcs, rowptr, aggm, n);
            k_sage_gemm<<<tiles, 512, SMEM_GEMM>>>(aggm, hin, pwg, blp, outs[l], n, 1);
            hin = outs[l];
        }
    }

    k_att<<<1024, 256>>>(o0, o1, w_att, b_att, (float4*)out_agg, n);
    k_heads<<<592, 256, SM_HEADS>>>((const float4*)out_agg,
                                    w_c1, b_c1, w_c2, b_c2,
                                    w_p1, b_p1, w_p2, b_p2,
                                    out_fraud, out_pat, n);
}

// round 9
// speedup vs baseline: 2.8459x; 1.2713x over previous
#include <cuda_runtime.h>
#include <cuda_fp16.h>
#include <cstdint>

#define NMAX 100000
#define EMAX 1600000
#define FULLMASK 0xffffffffu

// ---------------- scratch (static device allocations; no cudaMalloc) -------
__device__ __half g_h0[NMAX * 128];
__device__ __half g_hA[NMAX * 128];
__device__ __half g_hB[NMAX * 128];
__device__ __half g_o0[NMAX * 128];
__device__ __half g_o1[NMAX * 128];
__device__ __half g_agg[NMAX * 128];
__device__ __half g_pw[7 * 128 * 256];      // packed fp16 weights [g][nn][k]
__device__ int    g_counts[NMAX];
__device__ int    g_rowptr[NMAX + 1];
__device__ int    g_cursor[NMAX];
__device__ int    g_srcs[EMAX];
__device__ int    g_bsums[128];

// mma.sync m16n8k16 f16 -> f32 accum (portable, sm_80+)
__device__ __forceinline__ void mma_f16(float* d, const uint32_t* a, const uint32_t* b) {
    asm volatile(
        "mma.sync.aligned.m16n8k16.row.col.f32.f16.f16.f32 "
        "{%0,%1,%2,%3}, {%4,%5,%6,%7}, {%8,%9}, {%0,%1,%2,%3};"
        : "+f"(d[0]), "+f"(d[1]), "+f"(d[2]), "+f"(d[3])
        : "r"(a[0]), "r"(a[1]), "r"(a[2]), "r"(a[3]), "r"(b[0]), "r"(b[1]));
}

// smem geometry (halves): A[128][264] | B[128][264] | bias[128]f32
static constexpr int LDAH   = 264;
static constexpr int SMEM_GEMM = (2 * 128 * LDAH) * 2 + 128 * 4;   // 136192 B

// ---------------- weight pre-pack: fp32 [k][nn] -> fp16 [g][nn][k] ----------
// g = 0..5: sage (k<128 -> Wl[g], else Wr[g]); g = 6: embedding (k<128 w_emb, else 0)
__global__ void k_pack(const float* __restrict__ Wl, const float* __restrict__ Wr,
                       const float* __restrict__ w_emb, __half* __restrict__ pw)
{
    __shared__ float tile[32][33];
    const int g = blockIdx.z, k0 = blockIdx.x * 32, n0 = blockIdx.y * 32;
    const int tx = threadIdx.x, ty = threadIdx.y;
    #pragma unroll
    for (int i = 0; i < 4; ++i) {
        int k = k0 + ty + 8 * i, nn = n0 + tx;
        float v;
        if (g < 6) v = (k < 128) ? Wl[((size_t)g * 128 + k) * 128 + nn]
                                 : Wr[((size_t)g * 128 + (k - 128)) * 128 + nn];
        else       v = (k < 128) ? w_emb[(size_t)k * 128 + nn] : 0.f;
        tile[ty + 8 * i][tx] = v;
    }
    __syncthreads();
    #pragma unroll
    for (int i = 0; i < 4; ++i) {
        int k = k0 + tx, nn = n0 + ty + 8 * i;
        pw[((size_t)g * 128 + nn) * 256 + k] = __float2half_rn(tile[tx][ty + 8 * i]);
    }
}

// ---------------- standalone mean-aggregation gather ------------------------
// Warp per node: aggm[node] = mean_{j in in(node)} h[j]   (fp16 out, fp32 acc)
__global__ __launch_bounds__(256) void k_gather(
    const __half* __restrict__ hin, const int* __restrict__ srcs,
    const int* __restrict__ rowptr, __half* __restrict__ aggm, int n)
{
    const int lane = threadIdx.x & 31;
    const int node = blockIdx.x * 8 + (threadIdx.x >> 5);
    if (node >= n) return;
    const int beg = __ldg(&rowptr[node]);
    const int end = __ldg(&rowptr[node + 1]);
    float a0 = 0.f, a1 = 0.f, a2 = 0.f, a3 = 0.f;
    const uint2* hb = (const uint2*)hin;     // row stride = 32 uint2
    int e = beg;
    #pragma unroll 1
    for (; e + 4 <= end; e += 4) {
        int s0 = __ldg(&srcs[e + 0]);
        int s1 = __ldg(&srcs[e + 1]);
        int s2 = __ldg(&srcs[e + 2]);
        int s3 = __ldg(&srcs[e + 3]);
        uint2 u0 = __ldg(hb + (size_t)s0 * 32 + lane);
        uint2 u1 = __ldg(hb + (size_t)s1 * 32 + lane);
        uint2 u2 = __ldg(hb + (size_t)s2 * 32 + lane);
        uint2 u3 = __ldg(hb + (size_t)s3 * 32 + lane);
        float2 f;
        f = __half22float2(*(const __half2*)&u0.x); a0 += f.x; a1 += f.y;
        f = __half22float2(*(const __half2*)&u0.y); a2 += f.x; a3 += f.y;
        f = __half22float2(*(const __half2*)&u1.x); a0 += f.x; a1 += f.y;
        f = __half22float2(*(const __half2*)&u1.y); a2 += f.x; a3 += f.y;
        f = __half22float2(*(const __half2*)&u2.x); a0 += f.x; a1 += f.y;
        f = __half22float2(*(const __half2*)&u2.y); a2 += f.x; a3 += f.y;
        f = __half22float2(*(const __half2*)&u3.x); a0 += f.x; a1 += f.y;
        f = __half22float2(*(const __half2*)&u3.y); a2 += f.x; a3 += f.y;
    }
    for (; e < end; ++e) {
        uint2 u = __ldg(hb + (size_t)__ldg(&srcs[e]) * 32 + lane);
        float2 f;
        f = __half22float2(*(const __half2*)&u.x); a0 += f.x; a1 += f.y;
        f = __half22float2(*(const __half2*)&u.y); a2 += f.x; a3 += f.y;
    }
    const float inv = 1.0f / fmaxf((float)(end - beg), 1.0f);
    uint2 out;
    *(__half2*)&out.x = __floats2half2_rn(a0 * inv, a1 * inv);
    *(__half2*)&out.y = __floats2half2_rn(a2 * inv, a3 * inv);
    *((uint2*)(aggm + (size_t)node * 128) + lane) = out;
}

// ---------------- single fused K=256 GEMM layer (fp16 MMA) ------------------
// CTA = 128-node tile; out = relu([aggm|h] @ pwg^T + bias), pwg = [nn][k] fp16.
// do_agg=0 -> embedding: A = [x_fp16 | 0], pwg upper-k half is zero.
__global__ __launch_bounds__(512, 1) void k_sage_gemm(
    const __half* __restrict__ aggm, const void* __restrict__ hroot_v,
    const __half* __restrict__ pwg, const float* __restrict__ bias,
    __half* __restrict__ hout, int n, int do_agg)
{
    extern __shared__ __align__(16) char smem_raw[];
    __half* sA = (__half*)smem_raw;                 // [128][264]
    __half* sB = sA + 128 * LDAH;                   // [128][264]
    float*  sBias = (float*)(sB + 128 * LDAH);      // [128]
    const int tid = threadIdx.x;
    const int wid = tid >> 5;
    const int lane = tid & 31;

    // B copy: coalesced uint4, 128 rows x 32 chunks
    {
        const uint4* pw4 = (const uint4*)pwg;
        #pragma unroll
        for (int i = tid; i < 4096; i += 512) {
            int row = i >> 5, c = i & 31;
            ((uint4*)(sB + row * LDAH))[c] = __ldg(pw4 + i);
        }
    }
    if (tid < 128) sBias[tid] = bias[tid];

    // A staging: warp owns 8 rows; lanes span cols (4 halves each half-row)
    #pragma unroll
    for (int i = 0; i < 8; ++i) {
        const int row  = wid * 8 + i;
        const int node = blockIdx.x * 128 + row;
        uint2 ua = make_uint2(0u, 0u), uh = make_uint2(0u, 0u);
        if (node < n) {
            if (do_agg) {
                ua = __ldg((const uint2*)(aggm + (size_t)node * 128) + lane);
                uh = __ldg((const uint2*)((const __half*)hroot_v + (size_t)node * 128) + lane);
            } else {
                const float4 v = __ldg((const float4*)hroot_v + (size_t)node * 32 + lane);
                *(__half2*)&ua.x = __floats2half2_rn(v.x, v.y);
                *(__half2*)&ua.y = __floats2half2_rn(v.z, v.w);
            }
        }
        ((uint2*)(sA + row * LDAH))[lane] = ua;          // cols 0..127
        ((uint2*)(sA + row * LDAH + 128))[lane] = uh;    // cols 128..255
    }
    __syncthreads();

    // GEMM: warp wid -> rows (wid&3)*32.., cols (wid>>2)*32..; K=256, 16 ksteps
    const int wm = wid & 3;
    const int wn = wid >> 2;
    const int tr = lane >> 2;
    const int tc = lane & 3;
    float C[2][4][4];
    #pragma unroll
    for (int mt = 0; mt < 2; ++mt)
        #pragma unroll
        for (int nt = 0; nt < 4; ++nt)
            #pragma unroll
            for (int q = 0; q < 4; ++q) C[mt][nt][q] = 0.f;

    #pragma unroll 4
    for (int ks = 0; ks < 16; ++ks) {
        const int kb = ks * 16 + 2 * tc;
        uint32_t af[2][4], bf[4][2];
        #pragma unroll
        for (int mt = 0; mt < 2; ++mt) {
            const __half* p = sA + (wm * 32 + mt * 16 + tr) * LDAH + kb;
            af[mt][0] = *(const uint32_t*)(p);
            af[mt][1] = *(const uint32_t*)(p + 8 * LDAH);
            af[mt][2] = *(const uint32_t*)(p + 8);
            af[mt][3] = *(const uint32_t*)(p + 8 * LDAH + 8);
        }
        #pragma unroll
        for (int nt = 0; nt < 4; ++nt) {
            const __half* p = sB + (wn * 32 + nt * 8 + tr) * LDAH + kb;
            bf[nt][0] = *(const uint32_t*)(p);
            bf[nt][1] = *(const uint32_t*)(p + 8);
        }
        #pragma unroll
        for (int mt = 0; mt < 2; ++mt)
            #pragma unroll
            for (int nt = 0; nt < 4; ++nt)
                mma_f16(C[mt][nt], af[mt], bf[nt]);
    }

    // epilogue: bias + relu -> fp16
    #pragma unroll
    for (int mt = 0; mt < 2; ++mt) {
        int r0i = wm * 32 + mt * 16 + tr;
        int nd0 = blockIdx.x * 128 + r0i;
        int nd1 = nd0 + 8;
        #pragma unroll
        for (int nt = 0; nt < 4; ++nt) {
            int col = wn * 32 + nt * 8 + tc * 2;
            float b0 = sBias[col], b1 = sBias[col + 1];
            if (nd0 < n) {
                __half2 v = __floats2half2_rn(fmaxf(C[mt][nt][0] + b0, 0.f),
                                              fmaxf(C[mt][nt][1] + b1, 0.f));
                *(__half2*)(hout + (size_t)nd0 * 128 + col) = v;
            }
            if (nd1 < n) {
                __half2 v = __floats2half2_rn(fmaxf(C[mt][nt][2] + b0, 0.f),
                                              fmaxf(C[mt][nt][3] + b1, 0.f));
                *(__half2*)(hout + (size_t)nd1 * 128 + col) = v;
            }
        }
    }
}

// ---------------- CSR build: count + 3-stage scan + scatter ------------------
// invariant: g_counts all-zero on entry to k_count (zero-init; re-zeroed by k_scan3)
__global__ void k_count(const int* __restrict__ ed, int* __restrict__ counts, int E)
{
    int i = blockIdx.x * blockDim.x + threadIdx.x;
    if (i < E) atomicAdd(&counts[ed[E + i]], 1);
}

__global__ __launch_bounds__(1024) void k_scan1(
    const int* __restrict__ counts, int* __restrict__ rowptr,
    int* __restrict__ bsums, int n)
{
    __shared__ int s[1024];
    int i = blockIdx.x * 1024 + threadIdx.x;
    int v = (i < n) ? counts[i] : 0;
    s[threadIdx.x] = v;
    __syncthreads();
    #pragma unroll
    for (int off = 1; off < 1024; off <<= 1) {
        int t = (threadIdx.x >= off) ? s[threadIdx.x - off] : 0;
        __syncthreads();
        s[threadIdx.x] += t;
        __syncthreads();
    }
    if (i < n) rowptr[i] = s[threadIdx.x] - v;   // block-local exclusive
    if (threadIdx.x == 1023) bsums[blockIdx.x] = s[1023];
}

__global__ void k_scan2(int* __restrict__ bsums, int nb, int* __restrict__ rowptr, int n)
{
    if (threadIdx.x == 0 && blockIdx.x == 0) {
        int run = 0;
        for (int b = 0; b < nb; ++b) { int t = bsums[b]; bsums[b] = run; run += t; }
        rowptr[n] = run;
    }
}

__global__ void k_scan3(int* __restrict__ rowptr, const int* __restrict__ bsums,
                        int* __restrict__ cursor, int* __restrict__ counts, int n)
{
    int i = blockIdx.x * 1024 + threadIdx.x;
    if (i < n) {
        int v = rowptr[i] + bsums[blockIdx.x];
        rowptr[i] = v;
        cursor[i] = v;
        counts[i] = 0;          // restore invariant for next use / graph replay
    }
}

__global__ void k_scatter(const int* __restrict__ ed, int* __restrict__ cursor,
                          int* __restrict__ srcs, int E)
{
    int i = blockIdx.x * blockDim.x + threadIdx.x;
    if (i < E) {
        int d = ed[E + i];
        int p = atomicAdd(&cursor[d], 1);
        srcs[p] = ed[i];
    }
}

// ---------------- fused attention combine + classifier/pattern heads --------
__global__ __launch_bounds__(256) void k_att_heads(
    const __half* __restrict__ o0, const __half* __restrict__ o1,
    const float* __restrict__ watt, const float* __restrict__ batt,
    const float* __restrict__ wc1, const float* __restrict__ bc1,
    const float* __restrict__ wc2, const float* __restrict__ bc2,
    const float* __restrict__ wp1, const float* __restrict__ bp1,
    const float* __restrict__ wp2, const float* __restrict__ bp2,
    float4* __restrict__ agg, float* __restrict__ fraud, float* __restrict__ pat,
    int n)
{
    extern __shared__ float sm[];
    float* sC1 = sm;              // 128*64
    float* sP1 = sC1 + 8192;      // 128*64
    float* sC2 = sP1 + 8192;      // 64*2
    float* sP2 = sC2 + 128;       // 64*5
    float* sBC1 = sP2 + 320;      // 64
    float* sBP1 = sBC1 + 64;      // 64
    float* sBC2 = sBP1 + 64;      // 2
    float* sBP2 = sBC2 + 2;       // 5
    for (int i = threadIdx.x; i < 8192; i += blockDim.x) { sC1[i] = wc1[i]; sP1[i] = wp1[i]; }
    for (int i = threadIdx.x; i < 128;  i += blockDim.x) sC2[i] = wc2[i];
    for (int i = threadIdx.x; i < 320;  i += blockDim.x) sP2[i] = wp2[i];
    for (int i = threadIdx.x; i < 64;   i += blockDim.x) { sBC1[i] = bc1[i]; sBP1[i] = bp1[i]; }
    if (threadIdx.x < 2) sBC2[threadIdx.x] = bc2[threadIdx.x];
    if (threadIdx.x < 5) sBP2[threadIdx.x] = bp2[threadIdx.x];
    __syncthreads();

    const int lane = threadIdx.x & 31;
    const int gw = blockIdx.x * (blockDim.x >> 5) + (threadIdx.x >> 5);
    const int nw = gridDim.x * (blockDim.x >> 5);
    const float2* sC1v = (const float2*)sC1;
    const float2* sP1v = (const float2*)sP1;

    // per-lane attention weights (cols lane*4 .. lane*4+3 of each half)
    const int k0 = lane * 4;
    float wa0[4], wa1[4], wb0[4], wb1[4];
    #pragma unroll
    for (int c = 0; c < 4; ++c) {
        wa0[c] = __ldg(&watt[(k0 + c) * 2 + 0]);
        wa1[c] = __ldg(&watt[(k0 + c) * 2 + 1]);
        wb0[c] = __ldg(&watt[(128 + k0 + c) * 2 + 0]);
        wb1[c] = __ldg(&watt[(128 + k0 + c) * 2 + 1]);
    }
    const float bt0 = __ldg(&batt[0]), bt1 = __ldg(&batt[1]);

    // per-lane heads second-layer weights / biases
    const int hA = 2 * lane, hBb = 2 * lane + 1;
    const float c2a0 = sC2[hA * 2 + 0], c2a1 = sC2[hA * 2 + 1];
    const float c2b0 = sC2[hBb * 2 + 0], c2b1 = sC2[hBb * 2 + 1];
    float p2a[5], p2b[5];
    #pragma unroll
    for (int j = 0; j < 5; ++j) { p2a[j] = sP2[hA * 5 + j]; p2b[j] = sP2[hBb * 5 + j]; }
    const float bC1a = sBC1[hA], bC1b = sBC1[hBb];
    const float bP1a = sBP1[hA], bP1b = sBP1[hBb];
    const float bC2_0 = sBC2[0], bC2_1 = sBC2[1];
    float bP2v[5];
    #pragma unroll
    for (int j = 0; j < 5; ++j) bP2v[j] = sBP2[j];

    for (int node = gw; node < n; node += nw) {
        // ---- attention combine ----
        uint2 ua = __ldg((const uint2*)(o0 + (size_t)node * 128) + lane);
        uint2 ub = __ldg((const uint2*)(o1 + (size_t)node * 128) + lane);
        float2 a01 = __half22float2(*(const __half2*)&ua.x);
        float2 a23 = __half22float2(*(const __half2*)&ua.y);
        float2 b01 = __half22float2(*(const __half2*)&ub.x);
        float2 b23 = __half22float2(*(const __half2*)&ub.y);
        float p0 = a01.x * wa0[0] + a01.y * wa0[1] + a23.x * wa0[2] + a23.y * wa0[3]
                 + b01.x * wb0[0] + b01.y * wb0[1] + b23.x * wb0[2] + b23.y * wb0[3];
        float p1 = a01.x * wa1[0] + a01.y * wa1[1] + a23.x * wa1[2] + a23.y * wa1[3]
                 + b01.x * wb1[0] + b01.y * wb1[1] + b23.x * wb1[2] + b23.y * wb1[3];
        #pragma unroll
        for (int off = 16; off; off >>= 1) {
            p0 += __shfl_xor_sync(FULLMASK, p0, off);
            p1 += __shfl_xor_sync(FULLMASK, p1, off);
        }
        float z0 = p0 + bt0, z1 = p1 + bt1;
        float m = fmaxf(z0, z1);
        float e0 = expf(z0 - m), e1 = expf(z1 - m);
        float inv = 1.0f / (e0 + e1);
        float w0 = e0 * inv, w1 = e1 * inv;
        float4 ar;
        ar.x = w0 * a01.x + w1 * b01.x;
        ar.y = w0 * a01.y + w1 * b01.y;
        ar.z = w0 * a23.x + w1 * b23.x;
        ar.w = w0 * a23.y + w1 * b23.y;
        agg[node * 32 + lane] = ar;          // required output

        // ---- heads (first layer via shfl-broadcast GEMV) ----
        float hc0 = bC1a, hc1 = bC1b, hp0 = bP1a, hp1 = bP1b;
        #pragma unroll 4
        for (int kk = 0; kk < 32; ++kk) {
            float av[4];
            av[0] = __shfl_sync(FULLMASK, ar.x, kk);
            av[1] = __shfl_sync(FULLMASK, ar.y, kk);
            av[2] = __shfl_sync(FULLMASK, ar.z, kk);
            av[3] = __shfl_sync(FULLMASK, ar.w, kk);
            #pragma unroll
            for (int j = 0; j < 4; ++j) {
                int k = kk * 4 + j;
                float2 wc = sC1v[k * 32 + lane];
                float2 wp = sP1v[k * 32 + lane];
                hc0 += av[j] * wc.x; hc1 += av[j] * wc.y;
                hp0 += av[j] * wp.x; hp1 += av[j] * wp.y;
            }
        }
        hc0 = fmaxf(hc0, 0.f); hc1 = fmaxf(hc1, 0.f);
        hp0 = fmaxf(hp0, 0.f); hp1 = fmaxf(hp1, 0.f);

        float f0 = hc0 * c2a0 + hc1 * c2b0;
        float f1 = hc0 * c2a1 + hc1 * c2b1;
        float q[5];
        #pragma unroll
        for (int j = 0; j < 5; ++j) q[j] = hp0 * p2a[j] + hp1 * p2b[j];
        #pragma unroll
        for (int off = 16; off; off >>= 1) {
            f0 += __shfl_xor_sync(FULLMASK, f0, off);
            f1 += __shfl_xor_sync(FULLMASK, f1, off);
            #pragma unroll
            for (int j = 0; j < 5; ++j) q[j] += __shfl_xor_sync(FULLMASK, q[j], off);
        }
        if (lane == 0) {
            fraud[node * 2 + 0] = f0 + bC2_0;
            fraud[node * 2 + 1] = f1 + bC2_1;
            #pragma unroll
            for (int j = 0; j < 5; ++j) pat[node * 5 + j] = q[j] + bP2v[j];
        }
    }
}

// ---------------- launcher --------------------------------------------------
extern "C" void kernel_launch(void* const* d_in, const int* in_sizes, int n_in,
                              void* d_out, int out_size)
{
    const float* x     = (const float*)d_in[0];
    const int*   e0    = (const int*)  d_in[1];
    const int*   e1    = (const int*)  d_in[2];
    const float* w_emb = (const float*)d_in[3];
    const float* b_emb = (const float*)d_in[4];
    const float* Wl    = (const float*)d_in[5];
    const float* bl    = (const float*)d_in[6];
    const float* Wr    = (const float*)d_in[7];
    const float* w_att = (const float*)d_in[8];
    const float* b_att = (const float*)d_in[9];
    const float* w_c1  = (const float*)d_in[10];
    const float* b_c1  = (const float*)d_in[11];
    const float* w_c2  = (const float*)d_in[12];
    const float* b_c2  = (const float*)d_in[13];
    const float* w_p1  = (const float*)d_in[14];
    const float* b_p1  = (const float*)d_in[15];
    const float* w_p2  = (const float*)d_in[16];
    const float* b_p2  = (const float*)d_in[17];

    int n = in_sizes[0] / 128; if (n > NMAX) n = NMAX;
    int E = in_sizes[1] / 2;   if (E > EMAX) E = EMAX;

    float* out_fraud = (float*)d_out;
    float* out_pat   = out_fraud + (size_t)n * 2;
    float* out_agg   = out_pat   + (size_t)n * 5;

    __half *h0, *hA, *hB, *o0, *o1, *aggm, *pw;
    int *counts, *rowptr, *cursor, *srcs, *bsums;
    cudaGetSymbolAddress((void**)&h0, g_h0);
    cudaGetSymbolAddress((void**)&hA, g_hA);
    cudaGetSymbolAddress((void**)&hB, g_hB);
    cudaGetSymbolAddress((void**)&o0, g_o0);
    cudaGetSymbolAddress((void**)&o1, g_o1);
    cudaGetSymbolAddress((void**)&aggm, g_agg);
    cudaGetSymbolAddress((void**)&pw, g_pw);
    cudaGetSymbolAddress((void**)&counts, g_counts);
    cudaGetSymbolAddress((void**)&rowptr, g_rowptr);
    cudaGetSymbolAddress((void**)&cursor, g_cursor);
    cudaGetSymbolAddress((void**)&srcs, g_srcs);
    cudaGetSymbolAddress((void**)&bsums, g_bsums);

    const int SM_HEADS = (8192 + 8192 + 128 + 320 + 64 + 64 + 2 + 5) * 4;
    cudaFuncSetAttribute(k_sage_gemm, cudaFuncAttributeMaxDynamicSharedMemorySize, SMEM_GEMM);
    cudaFuncSetAttribute(k_att_heads, cudaFuncAttributeMaxDynamicSharedMemorySize, SM_HEADS);

    const int tiles = (n + 127) / 128;
    const int NB = (n + 1023) / 1024;

    // pack all weights (6 sage pairs + embedding) into fp16 [nn][k]
    k_pack<<<dim3(8, 4, 7), dim3(32, 8)>>>(Wl, Wr, w_emb, pw);

    // node embedding: relu(x @ w_emb + b_emb)
    k_sage_gemm<<<tiles, 512, SMEM_GEMM>>>(nullptr, x, pw + 6 * 32768, b_emb, h0, n, 0);

    for (int et = 0; et < 2; ++et) {
        const int* ed = et ? e1 : e0;
        k_count<<<(E + 255) / 256, 256>>>(ed, counts, E);
        k_scan1<<<NB, 1024>>>(counts, rowptr, bsums, n);
        k_scan2<<<1, 32>>>(bsums, NB, rowptr, n);
        k_scan3<<<NB, 1024>>>(rowptr, bsums, cursor, counts, n);
        k_scatter<<<(E + 255) / 256, 256>>>(ed, cursor, srcs, E);

        const __half* hin = h0;
        __half* outs[3] = { hA, hB, et ? o1 : o0 };
        for (int l = 0; l < 3; ++l) {
            const __half* pwg = pw + (size_t)(et * 3 + l) * 32768;
            const float* blp = bl + (size_t)(et * 3 + l) * 128;
            k_gather<<<(n + 7) / 8, 256>>>(hin, srcs, rowptr, aggm, n);
            k_sage_gemm<<<tiles, 512, SMEM_GEMM>>>(aggm, hin, pwg, blp, outs[l], n, 1);
            hin = outs[l];
        }
    }

    k_att_heads<<<592, 256, SM_HEADS>>>(o0, o1, w_att, b_att,
                                        w_c1, b_c1, w_c2, b_c2,
                                        w_p1, b_p1, w_p2, b_p2,
                                        (float4*)out_agg, out_fraud, out_pat, n);
}